// round 10
// baseline (speedup 1.0000x reference)
#include <cuda_runtime.h>
#include <cuda_bf16.h>
#include <math.h>

// B=16, T=32 (early exit: only token 31 used; all ops causal), DM=256,
// DI=512, DS=16, DR=16, DCONV=4, L=4. One persistent megakernel.
// This round: cp.async double-buffered GEMM (latency hidden), broadcast-LDS
// A operand (crossbar relief), staged float4 split-K consumers.

#define NB      16
#define TT      32
#define NTOK    (NB*TT)      // 512
#define DM      256
#define DI      512
#define DS      16
#define DR      16
#define NL      4
#define THREADS 256
#define SPLIT_IN  4
#define SPLIT_OUT 8
#define MAXG    512
#define FPAD    32

// scratch (device globals; no allocation allowed)
__device__ __align__(16) float g_feat[NTOK*DM];
__device__ __align__(16) float g_xzp [SPLIT_IN][NTOK*2*DI];
__device__ __align__(16) float g_dbl [NTOK*48];
__device__ __align__(16) float g_xct [NB*DI*TT];
__device__ __align__(16) float g_ztr [NB*DI*TT];
__device__ __align__(16) float g_dtt [NB*DI*TT];
__device__ __align__(16) float g_y   [NTOK*DI];
__device__ __align__(16) float g_outp[SPLIT_OUT][NTOK*DM];

__device__ unsigned g_flags[MAXG*FPAD];
__device__ unsigned g_rel;

__global__ void reset_bar() {
    for (int i = threadIdx.x; i < MAXG*FPAD; i += blockDim.x) g_flags[i] = 0u;
    if (threadIdx.x == 0) g_rel = 0u;
}

__device__ __forceinline__ void gsync(unsigned& gen) {
    __syncthreads();
    gen += 1u;
    const int bid = blockIdx.x;
    const int G   = gridDim.x;
    volatile unsigned* vf = (volatile unsigned*)g_flags;
    volatile unsigned* vr = (volatile unsigned*)&g_rel;
    if (bid == 0) {
        for (int i = threadIdx.x; i < G; i += THREADS)
            if (i != 0) { while (vf[i*FPAD] < gen) { } }
        __syncthreads();
        if (threadIdx.x == 0) { __threadfence(); *vr = gen; }
        __syncthreads();
    } else {
        if (threadIdx.x == 0) {
            __threadfence();
            vf[bid*FPAD] = gen;
            while (*vr < gen) { }
            __threadfence();
        }
        __syncthreads();
    }
}

// ---- packed dual-fp32 (FFMA2 via PTX) -------------------------------------
typedef unsigned long long ull;
__device__ __forceinline__ ull pk2(float lo, float hi) {
    ull r; asm("mov.b64 %0, {%1, %2};" : "=l"(r) : "f"(lo), "f"(hi)); return r;
}
__device__ __forceinline__ void fma2(ull& d, ull a, ull b) {
    asm("fma.rn.f32x2 %0, %1, %2, %0;" : "+l"(d) : "l"(a), "l"(b));
}
__device__ __forceinline__ float2 upk2(ull v) {
    float2 f; asm("mov.b64 {%0, %1}, %2;" : "=f"(f.x), "=f"(f.y) : "l"(v)); return f;
}

// smem: gemm uses As2 (2*128*20 = 5120) + BsT (2*16*132 = 4224) = 9344 floats
#define SMTOT 9344

__device__ __forceinline__ void cp_async16(float* dst, const float* src) {
    unsigned d = (unsigned)__cvta_generic_to_shared(dst);
    asm volatile("cp.async.cg.shared.global [%0], [%1], 16;" :: "r"(d), "l"(src));
}

// ---------------------------------------------------------------------------
// 128x128 tile SGEMM, cp.async double buffered.
// ---------------------------------------------------------------------------
__device__ __forceinline__ void gemm_tile128(const float* __restrict__ A,
                                             const float* __restrict__ B,
                                             float* __restrict__ C,
                                             int N, int K, int bm, int bn,
                                             int kbeg, int kend, float* sm)
{
    float* As2 = sm;            // [2][128][20] row-major, pad 20
    float* BsT = sm + 5120;     // [2][16][132] transposed
    const int tid = threadIdx.x;
    const int ty = tid >> 4, tx = tid & 15;
    const int c0 = tx*4, c1 = 64 + tx*4;
    const int ra = ty*4, rb = 64 + ty*4;

    ull acc[8][4];
    #pragma unroll
    for (int r = 0; r < 8; r++)
        #pragma unroll
        for (int c = 0; c < 4; c++) acc[r][c] = 0ull;

    // prologue: async-load A(kbeg) into buf 0
    #pragma unroll
    for (int j = 0; j < 2; j++) {
        int c = tid + j*256;                 // 512 chunks of 16B
        int row = c >> 2, q = c & 3;
        cp_async16(&As2[row*20 + q*4], A + (size_t)(bm+row)*K + kbeg + q*4);
    }
    asm volatile("cp.async.commit_group;" ::: "memory");

    int it = 0;
    for (int k0 = kbeg; k0 < kend; k0 += 16, it ^= 1) {
        // B: synchronous vector loads (weights)
        float4 bv[2];
        #pragma unroll
        for (int j = 0; j < 2; j++) {
            int i = tid + j*256;
            int n = i >> 2, q = i & 3;
            bv[j] = *(const float4*)(B + (size_t)(bn+n)*K + k0 + q*4);
        }
        // A: async-prefetch next k-block into other buffer
        if (k0 + 16 < kend) {
            int nb2 = it ^ 1;
            #pragma unroll
            for (int j = 0; j < 2; j++) {
                int c = tid + j*256;
                int row = c >> 2, q = c & 3;
                cp_async16(&As2[nb2*2560 + row*20 + q*4],
                           A + (size_t)(bm+row)*K + k0 + 16 + q*4);
            }
        }
        asm volatile("cp.async.commit_group;" ::: "memory");
        // store B transposed
        #pragma unroll
        for (int j = 0; j < 2; j++) {
            int i = tid + j*256;
            int n = i >> 2, q = i & 3;
            float* bp = &BsT[(size_t)it*2112 + (q*4)*132 + n];
            bp[0] = bv[j].x; bp[132] = bv[j].y; bp[264] = bv[j].z; bp[396] = bv[j].w;
        }
        asm volatile("cp.async.wait_group 1;" ::: "memory");
        __syncthreads();

        const float* Ab = &As2[it*2560];
        const float* Bb = &BsT[(size_t)it*2112];
        #pragma unroll
        for (int k = 0; k < 16; k++) {
            float4 bA = *(const float4*)&Bb[k*132 + c0];
            float4 bB = *(const float4*)&Bb[k*132 + c1];
            ull bp0 = pk2(bA.x,bA.y), bp1 = pk2(bA.z,bA.w);
            ull bp2 = pk2(bB.x,bB.y), bp3 = pk2(bB.z,bB.w);
            #pragma unroll
            for (int r = 0; r < 8; r++) {
                int row = (r < 4) ? (ra + r) : (rb + r - 4);
                float av = Ab[row*20 + k];      // 2-addr broadcast LDS
                ull a2 = pk2(av, av);
                fma2(acc[r][0], a2, bp0); fma2(acc[r][1], a2, bp1);
                fma2(acc[r][2], a2, bp2); fma2(acc[r][3], a2, bp3);
            }
        }
        __syncthreads();
    }
    #pragma unroll
    for (int r = 0; r < 8; r++) {
        int row = bm + ((r < 4) ? (ra + r) : (rb + r - 4));
        float2 p0 = upk2(acc[r][0]), p1 = upk2(acc[r][1]);
        float2 p2 = upk2(acc[r][2]), p3 = upk2(acc[r][3]);
        *(float4*)(C + (size_t)row*N + bn + c0) = make_float4(p0.x,p0.y,p1.x,p1.y);
        *(float4*)(C + (size_t)row*N + bn + c1) = make_float4(p2.x,p2.y,p3.x,p3.y);
    }
}

__device__ __forceinline__ void stage_gemm(const float* A, const float* W,
                                           float* Cp, int M, int N, int K,
                                           int S, float* sm)
{
    int ntn = N/128, nt = (M/128)*ntn;
    int ks = K / S;
    for (int w = blockIdx.x; w < nt*S; w += gridDim.x) {
        int s = w / nt, t = w - s*nt;
        int bm = (t / ntn)*128, bn = (t - (t/ntn)*ntn)*128;
        gemm_tile128(A, W, Cp + (size_t)s*M*N, N, K, bm, bn, s*ks, s*ks+ks, sm);
    }
}

// ---------------------------------------------------------------------------
__global__ void __launch_bounds__(THREADS, 2)
mega(const float* __restrict__ x,
     const float* __restrict__ ep,  const float* __restrict__ ef,
     const float* __restrict__ ed,
     const float* __restrict__ plw, const float* __restrict__ plb,
     const float* __restrict__ piw, const float* __restrict__ pib,
     const float* __restrict__ fw,  const float* __restrict__ fb,
     const float* __restrict__ tg,  const float* __restrict__ tb,
     const float* __restrict__ ng,  const float* __restrict__ nb,
     const float* __restrict__ ipw, const float* __restrict__ cw,
     const float* __restrict__ cb,  const float* __restrict__ xpw,
     const float* __restrict__ dtw, const float* __restrict__ dtb,
     const float* __restrict__ alog,const float* __restrict__ dp,
     const float* __restrict__ opw,
     const float* __restrict__ w1,  const float* __restrict__ b1,
     const float* __restrict__ w2,  const float* __restrict__ b2,
     float* __restrict__ out)
{
    __shared__ __align__(16) float SMF[SMTOT];
    unsigned gen = 0u;
    const int tid = threadIdx.x;
    const int G = gridDim.x;

    // ---------------- featurize + tok LN -> g_feat -----------------------
    {
        float* cat = SMF;          // 136
        float* red = SMF + 144;    // 256
        for (int tok = blockIdx.x; tok < NTOK; tok += G) {
            int b = tok >> 5, tl = tok & 31;
            const float* xr = x + (b*1024 + tl)*5;
            int d = tid;
            if (d < 136) {
                float v;
                if (d < 32)       { int p=(int)xr[0]; p=min(max(p,0),255); v=ep[p*32+d]; }
                else if (d < 64)  { v = xr[1]*plw[d-32] + plb[d-32]; }
                else if (d < 96)  { int f=(int)xr[2]; f=min(max(f,0),63); v=ef[f*32+(d-64)]; }
                else if (d < 128) { v = xr[3]*piw[d-96] + pib[d-96]; }
                else              { int dd=(int)xr[4]; dd=min(max(dd,0),1); v=ed[dd*8+(d-128)]; }
                cat[d] = v;
            }
            __syncthreads();
            float acc = fb[d];
            const float* wrow = fw + d*136;
            #pragma unroll 8
            for (int j = 0; j < 136; j++) acc += cat[j]*wrow[j];
            red[d] = acc; __syncthreads();
            for (int off=128; off; off>>=1){ if (d<off) red[d]+=red[d+off]; __syncthreads(); }
            float mean = red[0]*(1.f/DM); __syncthreads();
            float dv = acc-mean; red[d]=dv*dv; __syncthreads();
            for (int off=128; off; off>>=1){ if (d<off) red[d]+=red[d+off]; __syncthreads(); }
            float var = red[0]*(1.f/DM);
            g_feat[tok*DM + d] = dv*rsqrtf(var+1e-5f)*tg[d] + tb[d];
            __syncthreads();
        }
    }
    gsync(gen);

    for (int l = 0; l < NL; l++) {
        const float* ipw_l = ipw + (size_t)l*2*DI*DM;
        const float* cw_l  = cw  + (size_t)l*DI*4;
        const float* cb_l  = cb  + (size_t)l*DI;
        const float* xpw_l = xpw + (size_t)l*48*DI;
        const float* dtw_l = dtw + (size_t)l*DI*DR;
        const float* dtb_l = dtb + (size_t)l*DI;
        const float* al_l  = alog+ (size_t)l*DI*DS;
        const float* dp_l  = dp  + (size_t)l*DI;
        const float* opw_l = opw + (size_t)l*DM*DI;

        // -------- in_proj: split-K=4, 128 units --------------------------
        stage_gemm(g_feat, ipw_l, &g_xzp[0][0], NTOK, 2*DI, DM, SPLIT_IN, SMF);
        gsync(gen);

        // -------- conv+SiLU, x_proj, dt (staged float4 loads) ------------
        {
            float* rows = SMF;          // 4*512
            float* zrow = SMF + 2048;   // 512
            float* xcs  = SMF + 2560;   // 512
            float* dbls = SMF + 3072;   // 48
            for (int tok = blockIdx.x; tok < NTOK; tok += G) {
                int b = tok >> 5, tl = tok & 31;
                // stage 4 conv rows (split-summed, vectorized)
                for (int i = tid; i < 4*128; i += 256) {
                    int rr = i >> 7, q = i & 127;
                    int tt = tl - 3 + rr;
                    float4 s = make_float4(0.f,0.f,0.f,0.f);
                    if (tt >= 0) {
                        size_t off = (size_t)(tok-3+rr)*(2*DI) + q*4;
                        #pragma unroll
                        for (int sp = 0; sp < SPLIT_IN; sp++) {
                            float4 v = __ldcg((const float4*)(&g_xzp[sp][off]));
                            s.x += v.x; s.y += v.y; s.z += v.z; s.w += v.w;
                        }
                    }
                    *(float4*)&rows[rr*512 + q*4] = s;
                }
                // stage z row
                for (int q = tid; q < 128; q += 256) {
                    size_t off = (size_t)tok*(2*DI) + DI + q*4;
                    float4 s = make_float4(0.f,0.f,0.f,0.f);
                    #pragma unroll
                    for (int sp = 0; sp < SPLIT_IN; sp++) {
                        float4 v = __ldcg((const float4*)(&g_xzp[sp][off]));
                        s.x += v.x; s.y += v.y; s.z += v.z; s.w += v.w;
                    }
                    *(float4*)&zrow[q*4] = s;
                }
                __syncthreads();
                #pragma unroll
                for (int r = 0; r < 2; r++) {
                    int d = tid + r*256;
                    float acc = cb_l[d];
                    #pragma unroll
                    for (int k = 0; k < 4; k++)
                        acc += cw_l[d*4+k] * rows[k*512 + d];
                    xcs[d] = acc / (1.f + __expf(-acc));
                }
                __syncthreads();
                int warp = tid >> 5, lane = tid & 31;
                #pragma unroll
                for (int i = 0; i < 6; i++) {
                    int o = warp*6 + i;
                    const float* wr = xpw_l + o*DI;
                    float p = 0.f;
                    #pragma unroll
                    for (int j = 0; j < 16; j++) p += xcs[j*32+lane]*wr[j*32+lane];
                    #pragma unroll
                    for (int off = 16; off; off >>= 1)
                        p += __shfl_down_sync(0xffffffffu, p, off);
                    if (lane == 0) { dbls[o] = p; g_dbl[tok*48 + o] = p; }
                }
                __syncthreads();
                #pragma unroll
                for (int r = 0; r < 2; r++) {
                    int d = tid + r*256;
                    float v = dtb_l[d];
                    const float* dwr = dtw_l + d*DR;
                    #pragma unroll
                    for (int rr = 0; rr < DR; rr++) v += dbls[rr]*dwr[rr];
                    int tri = (b*DI + d)*TT + tl;
                    g_dtt[tri] = (v > 20.f) ? v : log1pf(__expf(v));
                    g_xct[tri] = xcs[d];
                    g_ztr[tri] = zrow[d];
                }
                __syncthreads();
            }
        }
        gsync(gen);

        // -------- selective scan: serial t, parallel (d,n) ---------------
        {
            float* Bsm = SMF;            // 512
            float* Csm = SMF + 512;      // 512
            float* ws  = SMF + 1024;     // 512
            float* es  = SMF + 1536;     // 512
            float* xs  = SMF + 2048;     // 512
            float* zs  = SMF + 2560;     // 512
            float* dts = SMF + 3072;     // 512
            float* A0s = SMF + 3584;     // 16
            for (int chunk = blockIdx.x; chunk < NB*32; chunk += G) {
                int b = chunk >> 5;
                int d0 = (chunk & 31) * 16;
                if (tid < 16) A0s[tid] = -__expf(al_l[(d0+tid)*DS]);
                __syncthreads();
                #pragma unroll
                for (int i = tid; i < 512; i += 256) {
                    int t = i >> 4, n = i & 15;
                    const float* row = g_dbl + (b*TT + t)*48;
                    Bsm[t*16+n] = __ldcg(&row[16+n]);
                    Csm[t*16+n] = __ldcg(&row[32+n]);
                    int ch = i >> 5, tt = i & 31;
                    int tri = (b*DI + d0 + ch)*TT + tt;
                    float dtv = __ldcg(&g_dtt[tri]);
                    float xv  = __ldcg(&g_xct[tri]);
                    dts[ch*32+tt] = dtv;
                    ws [ch*32+tt] = dtv*xv;
                    xs [ch*32+tt] = xv;
                    zs [ch*32+tt] = __ldcg(&g_ztr[tri]);
                    es [ch*32+tt] = __expf(dtv * A0s[ch]);
                }
                __syncthreads();
                int lane = tid & 31;
                int ch = (tid >> 5)*2 + (lane >> 4);
                int n = lane & 15;
                int d = d0 + ch;
                float An = -__expf(al_l[d*DS + n]);
                float A0 = A0s[ch];
                bool fast = fabsf(An - (float)(n+1)*A0) <= 1e-5f*fabsf(An) + 1e-7f;
                fast = __all_sync(0xffffffffu, fast);
                float Dd = dp_l[d];
                float h = 0.f;
                int np = n + 1;
                if (fast) {
                    #pragma unroll 4
                    for (int t = 0; t < TT; t++) {
                        float e1 = es[ch*32+t];
                        float p2 = e1*e1, p4 = p2*p2, p8 = p4*p4;
                        float a = 1.f;
                        if (np & 1)  a *= e1;
                        if (np & 2)  a *= p2;
                        if (np & 4)  a *= p4;
                        if (np & 8)  a *= p8;
                        if (np & 16) a *= p8*p8;
                        h = a*h + ws[ch*32+t]*Bsm[t*16+n];
                        float v = h*Csm[t*16+n];
                        v += __shfl_xor_sync(0xffffffffu, v, 8);
                        v += __shfl_xor_sync(0xffffffffu, v, 4);
                        v += __shfl_xor_sync(0xffffffffu, v, 2);
                        v += __shfl_xor_sync(0xffffffffu, v, 1);
                        if (n == 0) {
                            float zv = zs[ch*32+t];
                            float sz = zv / (1.f + __expf(-zv));
                            g_y[(b*TT+t)*DI + d] = (v + Dd*xs[ch*32+t]) * sz;
                        }
                    }
                } else {
                    #pragma unroll 4
                    for (int t = 0; t < TT; t++) {
                        float a = __expf(dts[ch*32+t]*An);
                        h = a*h + ws[ch*32+t]*Bsm[t*16+n];
                        float v = h*Csm[t*16+n];
                        v += __shfl_xor_sync(0xffffffffu, v, 8);
                        v += __shfl_xor_sync(0xffffffffu, v, 4);
                        v += __shfl_xor_sync(0xffffffffu, v, 2);
                        v += __shfl_xor_sync(0xffffffffu, v, 1);
                        if (n == 0) {
                            float zv = zs[ch*32+t];
                            float sz = zv / (1.f + __expf(-zv));
                            g_y[(b*TT+t)*DI + d] = (v + Dd*xs[ch*32+t]) * sz;
                        }
                    }
                }
                __syncthreads();
            }
        }
        gsync(gen);

        // -------- out_proj: split-K=8, 64 units --------------------------
        stage_gemm(g_y, opw_l, &g_outp[0][0], NTOK, DM, DI, SPLIT_OUT, SMF);
        gsync(gen);

        // -------- residual + LN -> feat (staged float4 split reads) ------
        {
            float* stg = SMF;           // 8*260 = 2080
            float* red = SMF + 2080;    // 256
            for (int tok = blockIdx.x; tok < NTOK; tok += G) {
                {
                    int sp = tid >> 5, i = tid & 31;
                    size_t base = (size_t)tok*DM + i*8;
                    float4 v0 = __ldcg((const float4*)(&g_outp[sp][base]));
                    float4 v1 = __ldcg((const float4*)(&g_outp[sp][base+4]));
                    *(float4*)&stg[sp*260 + i*8]     = v0;
                    *(float4*)&stg[sp*260 + i*8 + 4] = v1;
                }
                __syncthreads();
                int d = tid;
                size_t o = (size_t)tok*DM + d;
                float v = __ldcg(&g_feat[o]);
                #pragma unroll
                for (int sp = 0; sp < SPLIT_OUT; sp++) v += stg[sp*260 + d];
                red[d] = v; __syncthreads();
                for (int off=128; off; off>>=1){ if (d<off) red[d]+=red[d+off]; __syncthreads(); }
                float mean = red[0]*(1.f/DM); __syncthreads();
                float dv = v-mean; red[d]=dv*dv; __syncthreads();
                for (int off=128; off; off>>=1){ if (d<off) red[d]+=red[d+off]; __syncthreads(); }
                float var = red[0]*(1.f/DM);
                g_feat[o] = dv*rsqrtf(var+1e-5f)*ng[d] + nb[d];
                __syncthreads();
            }
        }
        gsync(gen);
    }

    // ---------------- classifier on token 31 ------------------------------
    if (blockIdx.x < NB) {
        float* hs = SMF;
        int b = blockIdx.x, j = tid;
        const float* fr = g_feat + (b*TT + 31)*DM;
        if (j < 128) {
            float acc = b1[j];
            const float* wr = w1 + j*DM;
            #pragma unroll 8
            for (int d = 0; d < DM; d++) acc += __ldcg(&fr[d])*wr[d];
            hs[j] = fmaxf(acc, 0.f);
        }
        __syncthreads();
        if (j < 2) {
            float o = b2[j];
            const float* w2r = w2 + j*128;
            #pragma unroll 8
            for (int k = 0; k < 128; k++) o += hs[k]*w2r[k];
            out[b*2 + j] = o;
        }
    }
}

// ---------------------------------------------------------------------------
extern "C" void kernel_launch(void* const* d_in, const int* in_sizes, int n_in,
                              void* d_out, int out_size)
{
    static int G = 0;
    if (!G) {
        int dev = 0; cudaGetDevice(&dev);
        int nsm = 0; cudaDeviceGetAttribute(&nsm, cudaDevAttrMultiProcessorCount, dev);
        int bpm = 0;
        cudaOccupancyMaxActiveBlocksPerMultiprocessor(&bpm, mega, THREADS, 0);
        if (bpm < 1) bpm = 1;
        if (bpm > 2) bpm = 2;
        G = nsm * bpm;
        if (G < 1) G = 1;
        if (G > MAXG) G = MAXG;
    }

    reset_bar<<<1, 256>>>();
    mega<<<G, THREADS>>>(
        (const float*)d_in[0],  (const float*)d_in[1],  (const float*)d_in[2],
        (const float*)d_in[3],  (const float*)d_in[4],  (const float*)d_in[5],
        (const float*)d_in[6],  (const float*)d_in[7],  (const float*)d_in[8],
        (const float*)d_in[9],  (const float*)d_in[10], (const float*)d_in[11],
        (const float*)d_in[12], (const float*)d_in[13], (const float*)d_in[14],
        (const float*)d_in[15], (const float*)d_in[16], (const float*)d_in[17],
        (const float*)d_in[18], (const float*)d_in[19], (const float*)d_in[20],
        (const float*)d_in[21], (const float*)d_in[22], (const float*)d_in[23],
        (const float*)d_in[24], (const float*)d_in[25], (const float*)d_in[26],
        (float*)d_out);
}

// round 12
// speedup vs baseline: 1.0772x; 1.0772x over previous
#include <cuda_runtime.h>
#include <cuda_bf16.h>
#include <math.h>

// B=16, T=32 (early exit: only token 31 used; all ops causal), DM=256,
// DI=512, DS=16, DR=16, DCONV=4, L=4. One persistent megakernel, grid-wide
// stages. R7 body verbatim; ONLY change: forced 4 CTAs/SM occupancy.

#define NB      16
#define TT      32
#define NTOK    (NB*TT)      // 512
#define DM      256
#define DI      512
#define DS      16
#define DR      16
#define NL      4
#define THREADS 256
#define SPLIT_IN  2
#define SPLIT_OUT 4

// scratch (device globals; no allocation allowed)
__device__ __align__(16) float g_feat[NTOK*DM];
__device__ __align__(16) float g_xzp [SPLIT_IN][NTOK*2*DI];
__device__ __align__(16) float g_dbl [NTOK*48];
__device__ __align__(16) float g_xct [NB*DI*TT];
__device__ __align__(16) float g_ztr [NB*DI*TT];
__device__ __align__(16) float g_dtt [NB*DI*TT];
__device__ __align__(16) float g_y   [NTOK*DI];
__device__ __align__(16) float g_outp[SPLIT_OUT][NTOK*DM];

__device__ unsigned          g_cnt;
__device__ volatile unsigned g_rel;

__global__ void reset_bar() { g_cnt = 0u; g_rel = 0u; }

// fast grid barrier: one atomic arrival per block; waiters poll with LDG
__device__ __forceinline__ void gsync(unsigned& gen) {
    __syncthreads();
    if (threadIdx.x == 0) {
        gen += 1u;
        __threadfence();
        unsigned a = atomicAdd(&g_cnt, 1u) + 1u;
        if (a == gen * gridDim.x) {
            __threadfence();
            g_rel = gen;
        } else {
            while (g_rel < gen) { }
        }
        __threadfence();
    }
    __syncthreads();
}

#define SMTOT 3664

// ---------------------------------------------------------------------------
// 64x64 tile SGEMM piece: C[bm:bm+64, bn:bn+64] = A[.,kbeg:kend] @ B^T
// A = activations (ldcg), B = weights (L1-cached).
// ---------------------------------------------------------------------------
__device__ __forceinline__ void gemm_tile(const float* __restrict__ A,
                                          const float* __restrict__ B,
                                          float* __restrict__ C,
                                          int N, int K, int bm, int bn,
                                          int kbeg, int kend, float* sm)
{
    float (*As)[68] = (float(*)[68])sm;
    float (*Bs)[68] = (float(*)[68])(sm + 16*68);
    int tid = threadIdx.x;
    int lr = tid >> 2, lk = (tid & 3) * 4;
    int ty = tid >> 4, tx = tid & 15;
    float acc[4][4] = {};
    for (int k0 = kbeg; k0 < kend; k0 += 16) {
        float4 av = __ldcg((const float4*)(A + (size_t)(bm+lr)*K + k0 + lk));
        float4 bv = *(const float4*)(B + (size_t)(bn+lr)*K + k0 + lk);
        As[lk+0][lr]=av.x; As[lk+1][lr]=av.y; As[lk+2][lr]=av.z; As[lk+3][lr]=av.w;
        Bs[lk+0][lr]=bv.x; Bs[lk+1][lr]=bv.y; Bs[lk+2][lr]=bv.z; Bs[lk+3][lr]=bv.w;
        __syncthreads();
        #pragma unroll
        for (int k = 0; k < 16; k++) {
            float4 a  = *(const float4*)&As[k][ty*4];
            float4 bb = *(const float4*)&Bs[k][tx*4];
            float ar[4] = {a.x,a.y,a.z,a.w};
            float br[4] = {bb.x,bb.y,bb.z,bb.w};
            #pragma unroll
            for (int r = 0; r < 4; r++)
                #pragma unroll
                for (int c = 0; c < 4; c++)
                    acc[r][c] += ar[r]*br[c];
        }
        __syncthreads();
    }
    #pragma unroll
    for (int r = 0; r < 4; r++)
        *(float4*)(C + (size_t)(bm+ty*4+r)*N + bn + tx*4) =
            make_float4(acc[r][0],acc[r][1],acc[r][2],acc[r][3]);
}

__device__ __forceinline__ void stage_gemm(const float* A, const float* W,
                                           float* Cp, int M, int N, int K,
                                           int S, float* sm)
{
    int ntn = N/64, nt = (M/64)*ntn;
    int ks = K / S;
    for (int w = blockIdx.x; w < nt*S; w += gridDim.x) {
        int s = w / nt, t = w - s*nt;
        int bm = (t / ntn)*64, bn = (t - (t/ntn)*ntn)*64;
        gemm_tile(A, W, Cp + (size_t)s*M*N, N, K, bm, bn, s*ks, s*ks+ks, sm);
    }
}

// ---------------------------------------------------------------------------
__global__ void __launch_bounds__(THREADS, 4)
mega(const float* __restrict__ x,
     const float* __restrict__ ep,  const float* __restrict__ ef,
     const float* __restrict__ ed,
     const float* __restrict__ plw, const float* __restrict__ plb,
     const float* __restrict__ piw, const float* __restrict__ pib,
     const float* __restrict__ fw,  const float* __restrict__ fb,
     const float* __restrict__ tg,  const float* __restrict__ tb,
     const float* __restrict__ ng,  const float* __restrict__ nb,
     const float* __restrict__ ipw, const float* __restrict__ cw,
     const float* __restrict__ cb,  const float* __restrict__ xpw,
     const float* __restrict__ dtw, const float* __restrict__ dtb,
     const float* __restrict__ alog,const float* __restrict__ dp,
     const float* __restrict__ opw,
     const float* __restrict__ w1,  const float* __restrict__ b1,
     const float* __restrict__ w2,  const float* __restrict__ b2,
     float* __restrict__ out)
{
    __shared__ __align__(16) float SMF[SMTOT];
    unsigned gen = 0u;
    const int tid = threadIdx.x;
    const int G = gridDim.x;

    // ---------------- featurize + tok LN -> g_feat -----------------------
    {
        float* cat = SMF;          // 136
        float* red = SMF + 144;    // 256
        for (int tok = blockIdx.x; tok < NTOK; tok += G) {
            int b = tok >> 5, tl = tok & 31;
            const float* xr = x + (b*1024 + tl)*5;
            int d = tid;
            if (d < 136) {
                float v;
                if (d < 32)       { int p=(int)xr[0]; p=min(max(p,0),255); v=ep[p*32+d]; }
                else if (d < 64)  { v = xr[1]*plw[d-32] + plb[d-32]; }
                else if (d < 96)  { int f=(int)xr[2]; f=min(max(f,0),63); v=ef[f*32+(d-64)]; }
                else if (d < 128) { v = xr[3]*piw[d-96] + pib[d-96]; }
                else              { int dd=(int)xr[4]; dd=min(max(dd,0),1); v=ed[dd*8+(d-128)]; }
                cat[d] = v;
            }
            __syncthreads();
            float acc = fb[d];
            const float* wrow = fw + d*136;
            #pragma unroll 8
            for (int j = 0; j < 136; j++) acc += cat[j]*wrow[j];
            red[d] = acc; __syncthreads();
            for (int off=128; off; off>>=1){ if (d<off) red[d]+=red[d+off]; __syncthreads(); }
            float mean = red[0]*(1.f/DM); __syncthreads();
            float dv = acc-mean; red[d]=dv*dv; __syncthreads();
            for (int off=128; off; off>>=1){ if (d<off) red[d]+=red[d+off]; __syncthreads(); }
            float var = red[0]*(1.f/DM);
            g_feat[tok*DM + d] = dv*rsqrtf(var+1e-5f)*tg[d] + tb[d];
            __syncthreads();
        }
    }
    gsync(gen);

    for (int l = 0; l < NL; l++) {
        const float* ipw_l = ipw + (size_t)l*2*DI*DM;
        const float* cw_l  = cw  + (size_t)l*DI*4;
        const float* cb_l  = cb  + (size_t)l*DI;
        const float* xpw_l = xpw + (size_t)l*48*DI;
        const float* dtw_l = dtw + (size_t)l*DI*DR;
        const float* dtb_l = dtb + (size_t)l*DI;
        const float* al_l  = alog+ (size_t)l*DI*DS;
        const float* dp_l  = dp  + (size_t)l*DI;
        const float* opw_l = opw + (size_t)l*DM*DI;

        // -------- in_proj: xz = feat @ ipw^T (split-K=2 partials) --------
        stage_gemm(g_feat, ipw_l, &g_xzp[0][0], NTOK, 2*DI, DM, SPLIT_IN, SMF);
        gsync(gen);

        // -------- conv+SiLU, x_proj, dt (per token) ----------------------
        {
            float* xcs  = SMF;        // 512
            float* dbls = SMF + 512;  // 48
            for (int tok = blockIdx.x; tok < NTOK; tok += G) {
                int b = tok >> 5, tl = tok & 31;
                #pragma unroll
                for (int r = 0; r < 2; r++) {
                    int d = tid + r*256;
                    float acc = cb_l[d];
                    #pragma unroll
                    for (int k = 0; k < 4; k++) {
                        int tt = tl - 3 + k;
                        if (tt >= 0) {
                            int off = (tok-3+k)*(2*DI) + d;
                            float s = 0.f;
                            #pragma unroll
                            for (int sp = 0; sp < SPLIT_IN; sp++)
                                s += __ldcg(&g_xzp[sp][off]);
                            acc += cw_l[d*4+k] * s;
                        }
                    }
                    xcs[d] = acc / (1.f + __expf(-acc));
                }
                __syncthreads();
                int warp = tid >> 5, lane = tid & 31;
                #pragma unroll
                for (int i = 0; i < 6; i++) {
                    int o = warp*6 + i;
                    const float* wr = xpw_l + o*DI;
                    float p = 0.f;
                    #pragma unroll
                    for (int j = 0; j < 16; j++) p += xcs[j*32+lane]*wr[j*32+lane];
                    #pragma unroll
                    for (int off = 16; off; off >>= 1)
                        p += __shfl_down_sync(0xffffffffu, p, off);
                    if (lane == 0) { dbls[o] = p; g_dbl[tok*48 + o] = p; }
                }
                __syncthreads();
                #pragma unroll
                for (int r = 0; r < 2; r++) {
                    int d = tid + r*256;
                    float v = dtb_l[d];
                    const float* dwr = dtw_l + d*DR;
                    #pragma unroll
                    for (int rr = 0; rr < DR; rr++) v += dbls[rr]*dwr[rr];
                    int tri = (b*DI + d)*TT + tl;
                    g_dtt[tri] = (v > 20.f) ? v : log1pf(__expf(v));
                    g_xct[tri] = xcs[d];
                    int zo = tok*2*DI + DI + d;
                    float zv = 0.f;
                    #pragma unroll
                    for (int sp = 0; sp < SPLIT_IN; sp++)
                        zv += __ldcg(&g_xzp[sp][zo]);
                    g_ztr[tri] = zv;
                }
                __syncthreads();
            }
        }
        gsync(gen);

        // -------- selective scan: serial t, parallel (d,n) ---------------
        {
            float* Bsm = SMF;            // 512
            float* Csm = SMF + 512;      // 512
            float* ws  = SMF + 1024;     // 512
            float* es  = SMF + 1536;     // 512
            float* xs  = SMF + 2048;     // 512
            float* zs  = SMF + 2560;     // 512
            float* dts = SMF + 3072;     // 512
            float* A0s = SMF + 3584;     // 16
            for (int chunk = blockIdx.x; chunk < NB*32; chunk += G) {
                int b = chunk >> 5;
                int d0 = (chunk & 31) * 16;
                if (tid < 16) A0s[tid] = -__expf(al_l[(d0+tid)*DS]);
                __syncthreads();
                #pragma unroll
                for (int i = tid; i < 512; i += 256) {
                    int t = i >> 4, n = i & 15;
                    const float* row = g_dbl + (b*TT + t)*48;
                    Bsm[t*16+n] = __ldcg(&row[16+n]);
                    Csm[t*16+n] = __ldcg(&row[32+n]);
                    int ch = i >> 5, tt = i & 31;
                    int tri = (b*DI + d0 + ch)*TT + tt;
                    float dtv = __ldcg(&g_dtt[tri]);
                    float xv  = __ldcg(&g_xct[tri]);
                    dts[ch*32+tt] = dtv;
                    ws [ch*32+tt] = dtv*xv;
                    xs [ch*32+tt] = xv;
                    zs [ch*32+tt] = __ldcg(&g_ztr[tri]);
                    es [ch*32+tt] = __expf(dtv * A0s[ch]);
                }
                __syncthreads();
                int lane = tid & 31;
                int ch = (tid >> 5)*2 + (lane >> 4);
                int n = lane & 15;
                int d = d0 + ch;
                float An = -__expf(al_l[d*DS + n]);
                float A0 = A0s[ch];
                bool fast = fabsf(An - (float)(n+1)*A0) <= 1e-5f*fabsf(An) + 1e-7f;
                fast = __all_sync(0xffffffffu, fast);
                float Dd = dp_l[d];
                float h = 0.f;
                int np = n + 1;
                if (fast) {
                    #pragma unroll 4
                    for (int t = 0; t < TT; t++) {
                        float e1 = es[ch*32+t];
                        float p2 = e1*e1, p4 = p2*p2, p8 = p4*p4;
                        float a = 1.f;
                        if (np & 1)  a *= e1;
                        if (np & 2)  a *= p2;
                        if (np & 4)  a *= p4;
                        if (np & 8)  a *= p8;
                        if (np & 16) a *= p8*p8;
                        h = a*h + ws[ch*32+t]*Bsm[t*16+n];
                        float v = h*Csm[t*16+n];
                        v += __shfl_xor_sync(0xffffffffu, v, 8);
                        v += __shfl_xor_sync(0xffffffffu, v, 4);
                        v += __shfl_xor_sync(0xffffffffu, v, 2);
                        v += __shfl_xor_sync(0xffffffffu, v, 1);
                        if (n == 0) {
                            float zv = zs[ch*32+t];
                            float sz = zv / (1.f + __expf(-zv));
                            g_y[(b*TT+t)*DI + d] = (v + Dd*xs[ch*32+t]) * sz;
                        }
                    }
                } else {
                    #pragma unroll 4
                    for (int t = 0; t < TT; t++) {
                        float a = __expf(dts[ch*32+t]*An);
                        h = a*h + ws[ch*32+t]*Bsm[t*16+n];
                        float v = h*Csm[t*16+n];
                        v += __shfl_xor_sync(0xffffffffu, v, 8);
                        v += __shfl_xor_sync(0xffffffffu, v, 4);
                        v += __shfl_xor_sync(0xffffffffu, v, 2);
                        v += __shfl_xor_sync(0xffffffffu, v, 1);
                        if (n == 0) {
                            float zv = zs[ch*32+t];
                            float sz = zv / (1.f + __expf(-zv));
                            g_y[(b*TT+t)*DI + d] = (v + Dd*xs[ch*32+t]) * sz;
                        }
                    }
                }
                __syncthreads();
            }
        }
        gsync(gen);

        // -------- out_proj: split-K=4 partials ---------------------------
        stage_gemm(g_y, opw_l, &g_outp[0][0], NTOK, DM, DI, SPLIT_OUT, SMF);
        gsync(gen);

        // -------- residual + LN -> feat ----------------------------------
        {
            float* red = SMF;
            for (int tok = blockIdx.x; tok < NTOK; tok += G) {
                int d = tid;
                int o = tok*DM + d;
                float v = __ldcg(&g_feat[o]) + __ldcg(&g_outp[0][o]) + __ldcg(&g_outp[1][o])
                        + __ldcg(&g_outp[2][o]) + __ldcg(&g_outp[3][o]);
                red[d] = v; __syncthreads();
                for (int off=128; off; off>>=1){ if (d<off) red[d]+=red[d+off]; __syncthreads(); }
                float mean = red[0]*(1.f/DM); __syncthreads();
                float dv = v-mean; red[d]=dv*dv; __syncthreads();
                for (int off=128; off; off>>=1){ if (d<off) red[d]+=red[d+off]; __syncthreads(); }
                float var = red[0]*(1.f/DM);
                g_feat[o] = dv*rsqrtf(var+1e-5f)*ng[d] + nb[d];
                __syncthreads();
            }
        }
        gsync(gen);
    }

    // ---------------- classifier on token 31 ------------------------------
    if (blockIdx.x < NB) {
        float* hs = SMF;
        int b = blockIdx.x, j = tid;
        const float* fr = g_feat + (b*TT + 31)*DM;
        if (j < 128) {
            float acc = b1[j];
            const float* wr = w1 + j*DM;
            #pragma unroll 8
            for (int d = 0; d < DM; d++) acc += __ldcg(&fr[d])*wr[d];
            hs[j] = fmaxf(acc, 0.f);
        }
        __syncthreads();
        if (j < 2) {
            float o = b2[j];
            const float* w2r = w2 + j*128;
            #pragma unroll 8
            for (int k = 0; k < 128; k++) o += hs[k]*w2r[k];
            out[b*2 + j] = o;
        }
    }
}

// ---------------------------------------------------------------------------
extern "C" void kernel_launch(void* const* d_in, const int* in_sizes, int n_in,
                              void* d_out, int out_size)
{
    static int G = 0;
    if (!G) {
        int dev = 0; cudaGetDevice(&dev);
        int nsm = 0; cudaDeviceGetAttribute(&nsm, cudaDevAttrMultiProcessorCount, dev);
        int bpm = 0;
        cudaOccupancyMaxActiveBlocksPerMultiprocessor(&bpm, mega, THREADS, 0);
        if (bpm < 1) bpm = 1;
        if (bpm > 4) bpm = 4;
        G = nsm * bpm;
        if (G < 1) G = 1;
        if (G > 1024) G = 1024;
    }

    reset_bar<<<1,1>>>();
    mega<<<G, THREADS>>>(
        (const float*)d_in[0],  (const float*)d_in[1],  (const float*)d_in[2],
        (const float*)d_in[3],  (const float*)d_in[4],  (const float*)d_in[5],
        (const float*)d_in[6],  (const float*)d_in[7],  (const float*)d_in[8],
        (const float*)d_in[9],  (const float*)d_in[10], (const float*)d_in[11],
        (const float*)d_in[12], (const float*)d_in[13], (const float*)d_in[14],
        (const float*)d_in[15], (const float*)d_in[16], (const float*)d_in[17],
        (const float*)d_in[18], (const float*)d_in[19], (const float*)d_in[20],
        (const float*)d_in[21], (const float*)d_in[22], (const float*)d_in[23],
        (const float*)d_in[24], (const float*)d_in[25], (const float*)d_in[26],
        (float*)d_out);
}

// round 13
// speedup vs baseline: 1.1564x; 1.0735x over previous
#include <cuda_runtime.h>
#include <cuda_bf16.h>
#include <math.h>

// B=16, T=32 (early exit: only token 31 used; all ops causal), DM=256,
// DI=512, DS=16, DR=16, DCONV=4, L=4.
// One persistent kernel; 16 INDEPENDENT per-batch pipelines of 32 CTAs each
// (grid 512, 4 CTAs/SM => all resident). All syncs are per-batch (32 arrivals)
// so stage intervals don't couple across batches.

#define NB      16
#define TT      32
#define NTOK    (NB*TT)      // 512
#define DM      256
#define DI      512
#define DS      16
#define DR      16
#define NL      4
#define THREADS 256
#define CPB     32           // CTAs per batch
#define SPLIT_IN  2
#define SPLIT_OUT 8
#define FPAD    32           // 128B pad between per-batch counters

// scratch (device globals; no allocation allowed)
__device__ __align__(16) float g_feat[NTOK*DM];
__device__ __align__(16) float g_xzp [SPLIT_IN][NTOK*2*DI];
__device__ __align__(16) float g_dbl [NTOK*48];
__device__ __align__(16) float g_xct [NB*DI*TT];
__device__ __align__(16) float g_ztr [NB*DI*TT];
__device__ __align__(16) float g_dtt [NB*DI*TT];
__device__ __align__(16) float g_y   [NTOK*DI];
__device__ __align__(16) float g_outp[SPLIT_OUT][NTOK*DM];

__device__ unsigned g_cnt[NB*FPAD];
__device__ unsigned g_rel[NB*FPAD];

__global__ void reset_bar() {
    for (int i = threadIdx.x; i < NB*FPAD; i += blockDim.x) {
        g_cnt[i] = 0u; g_rel[i] = 0u;
    }
}

// per-batch barrier: 32 atomic arrivals on the batch's counter; last arriver
// publishes release; waiters load-poll the release word.
__device__ __forceinline__ void bsync(int b, unsigned& gen) {
    __syncthreads();
    gen += 1u;
    if (threadIdx.x == 0) {
        __threadfence();
        unsigned a = atomicAdd(&g_cnt[b*FPAD], 1u) + 1u;
        if (a == gen * CPB) {
            __threadfence();
            *(volatile unsigned*)&g_rel[b*FPAD] = gen;
        } else {
            while (*(volatile unsigned*)&g_rel[b*FPAD] < gen) { }
        }
        __threadfence();
    }
    __syncthreads();
}

#define SMTOT 3664

// ---------------------------------------------------------------------------
// 32x64 tile SGEMM: C[bm:+32, bn:+64] = A[.,kbeg:kend] @ B^T
// 256 thr; 2x4 microtile; A scalar-broadcast reads, B vector reads.
// ---------------------------------------------------------------------------
__device__ __forceinline__ void gemm_tile32(const float* __restrict__ A,
                                            const float* __restrict__ B,
                                            float* __restrict__ C,
                                            int N, int K, int bm, int bn,
                                            int kbeg, int kend, float* sm)
{
    float (*As)[36] = (float(*)[36])sm;            // [16][36]: As[k][m]
    float (*Bs)[68] = (float(*)[68])(sm + 16*36);  // [16][68]: Bs[k][n]
    const int tid = threadIdx.x;
    const int ty = tid >> 4, tx = tid & 15;
    float acc[2][4] = {};
    for (int k0 = kbeg; k0 < kend; k0 += 16) {
        if (tid < 128) {                 // A: 32x16 = 128 float4
            int lr = tid >> 2, lk = (tid & 3)*4;
            float4 av = __ldcg((const float4*)(A + (size_t)(bm+lr)*K + k0 + lk));
            As[lk+0][lr]=av.x; As[lk+1][lr]=av.y; As[lk+2][lr]=av.z; As[lk+3][lr]=av.w;
        }
        {                                 // B: 64x16 = 256 float4
            int lr = tid >> 2, lk = (tid & 3)*4;
            float4 bv = *(const float4*)(B + (size_t)(bn+lr)*K + k0 + lk);
            Bs[lk+0][lr]=bv.x; Bs[lk+1][lr]=bv.y; Bs[lk+2][lr]=bv.z; Bs[lk+3][lr]=bv.w;
        }
        __syncthreads();
        #pragma unroll
        for (int k = 0; k < 16; k++) {
            float a0 = As[k][ty*2], a1 = As[k][ty*2+1];
            float4 bb = *(const float4*)&Bs[k][tx*4];
            acc[0][0] += a0*bb.x; acc[0][1] += a0*bb.y;
            acc[0][2] += a0*bb.z; acc[0][3] += a0*bb.w;
            acc[1][0] += a1*bb.x; acc[1][1] += a1*bb.y;
            acc[1][2] += a1*bb.z; acc[1][3] += a1*bb.w;
        }
        __syncthreads();
    }
    #pragma unroll
    for (int r = 0; r < 2; r++)
        *(float4*)(C + (size_t)(bm+ty*2+r)*N + bn + tx*4) =
            make_float4(acc[r][0],acc[r][1],acc[r][2],acc[r][3]);
}

// ---------------------------------------------------------------------------
__global__ void __launch_bounds__(THREADS, 4)
mega(const float* __restrict__ x,
     const float* __restrict__ ep,  const float* __restrict__ ef,
     const float* __restrict__ ed,
     const float* __restrict__ plw, const float* __restrict__ plb,
     const float* __restrict__ piw, const float* __restrict__ pib,
     const float* __restrict__ fw,  const float* __restrict__ fb,
     const float* __restrict__ tg,  const float* __restrict__ tb,
     const float* __restrict__ ng,  const float* __restrict__ nb,
     const float* __restrict__ ipw, const float* __restrict__ cw,
     const float* __restrict__ cb,  const float* __restrict__ xpw,
     const float* __restrict__ dtw, const float* __restrict__ dtb,
     const float* __restrict__ alog,const float* __restrict__ dp,
     const float* __restrict__ opw,
     const float* __restrict__ w1,  const float* __restrict__ b1,
     const float* __restrict__ w2,  const float* __restrict__ b2,
     float* __restrict__ out)
{
    __shared__ __align__(16) float SMF[SMTOT];
    unsigned gen = 0u;
    const int tid  = threadIdx.x;
    const int b    = blockIdx.x >> 5;   // batch
    const int rank = blockIdx.x & 31;   // CTA within batch

    // ---------------- featurize + tok LN (1 token per rank) --------------
    {
        float* cat = SMF;          // 136
        float* red = SMF + 144;    // 256
        int tl = rank;
        int tok = b*TT + tl;
        const float* xr = x + (b*1024 + tl)*5;
        int d = tid;
        if (d < 136) {
            float v;
            if (d < 32)       { int p=(int)xr[0]; p=min(max(p,0),255); v=ep[p*32+d]; }
            else if (d < 64)  { v = xr[1]*plw[d-32] + plb[d-32]; }
            else if (d < 96)  { int f=(int)xr[2]; f=min(max(f,0),63); v=ef[f*32+(d-64)]; }
            else if (d < 128) { v = xr[3]*piw[d-96] + pib[d-96]; }
            else              { int dd=(int)xr[4]; dd=min(max(dd,0),1); v=ed[dd*8+(d-128)]; }
            cat[d] = v;
        }
        __syncthreads();
        float acc = fb[d];
        const float* wrow = fw + d*136;
        #pragma unroll 8
        for (int j = 0; j < 136; j++) acc += cat[j]*wrow[j];
        red[d] = acc; __syncthreads();
        for (int off=128; off; off>>=1){ if (d<off) red[d]+=red[d+off]; __syncthreads(); }
        float mean = red[0]*(1.f/DM); __syncthreads();
        float dv = acc-mean; red[d]=dv*dv; __syncthreads();
        for (int off=128; off; off>>=1){ if (d<off) red[d]+=red[d+off]; __syncthreads(); }
        float var = red[0]*(1.f/DM);
        g_feat[tok*DM + d] = dv*rsqrtf(var+1e-5f)*tg[d] + tb[d];
    }
    bsync(b, gen);

    for (int l = 0; l < NL; l++) {
        const float* ipw_l = ipw + (size_t)l*2*DI*DM;
        const float* cw_l  = cw  + (size_t)l*DI*4;
        const float* cb_l  = cb  + (size_t)l*DI;
        const float* xpw_l = xpw + (size_t)l*48*DI;
        const float* dtw_l = dtw + (size_t)l*DI*DR;
        const float* dtb_l = dtb + (size_t)l*DI;
        const float* al_l  = alog+ (size_t)l*DI*DS;
        const float* dp_l  = dp  + (size_t)l*DI;
        const float* opw_l = opw + (size_t)l*DM*DI;

        // -------- in_proj: 16 N-tiles x splitK2 = 32 units (1 per rank) --
        {
            int s = rank >> 4;            // split half
            int t = rank & 15;            // N tile
            gemm_tile32(g_feat, ipw_l, &g_xzp[s][0], 2*DI, DM,
                        b*TT, t*64, s*128, s*128+128, SMF);
        }
        bsync(b, gen);

        // -------- conv+SiLU, x_proj, dt (1 token per rank) ---------------
        {
            float* xcs  = SMF;        // 512
            float* dbls = SMF + 512;  // 48
            int tl = rank;
            int tok = b*TT + tl;
            #pragma unroll
            for (int r = 0; r < 2; r++) {
                int d = tid + r*256;
                float acc = cb_l[d];
                #pragma unroll
                for (int k = 0; k < 4; k++) {
                    int tt = tl - 3 + k;
                    if (tt >= 0) {
                        int off = (tok-3+k)*(2*DI) + d;
                        acc += cw_l[d*4+k] *
                               (__ldcg(&g_xzp[0][off]) + __ldcg(&g_xzp[1][off]));
                    }
                }
                xcs[d] = acc / (1.f + __expf(-acc));
            }
            __syncthreads();
            int warp = tid >> 5, lane = tid & 31;
            #pragma unroll
            for (int i = 0; i < 6; i++) {
                int o = warp*6 + i;
                const float* wr = xpw_l + o*DI;
                float p = 0.f;
                #pragma unroll
                for (int j = 0; j < 16; j++) p += xcs[j*32+lane]*wr[j*32+lane];
                #pragma unroll
                for (int off = 16; off; off >>= 1)
                    p += __shfl_down_sync(0xffffffffu, p, off);
                if (lane == 0) { dbls[o] = p; g_dbl[tok*48 + o] = p; }
            }
            __syncthreads();
            #pragma unroll
            for (int r = 0; r < 2; r++) {
                int d = tid + r*256;
                float v = dtb_l[d];
                const float* dwr = dtw_l + d*DR;
                #pragma unroll
                for (int rr = 0; rr < DR; rr++) v += dbls[rr]*dwr[rr];
                int tri = (b*DI + d)*TT + tl;
                g_dtt[tri] = (v > 20.f) ? v : log1pf(__expf(v));
                g_xct[tri] = xcs[d];
                int zo = tok*2*DI + DI + d;
                g_ztr[tri] = __ldcg(&g_xzp[0][zo]) + __ldcg(&g_xzp[1][zo]);
            }
        }
        bsync(b, gen);

        // -------- selective scan: 16 channels per rank -------------------
        {
            float* Bsm = SMF;            // 512
            float* Csm = SMF + 512;      // 512
            float* ws  = SMF + 1024;     // 512
            float* es  = SMF + 1536;     // 512
            float* xs  = SMF + 2048;     // 512
            float* zs  = SMF + 2560;     // 512
            float* dts = SMF + 3072;     // 512
            float* A0s = SMF + 3584;     // 16
            int d0 = rank * 16;
            if (tid < 16) A0s[tid] = -__expf(al_l[(d0+tid)*DS]);
            __syncthreads();
            #pragma unroll
            for (int i = tid; i < 512; i += 256) {
                int t = i >> 4, n = i & 15;
                const float* row = g_dbl + (b*TT + t)*48;
                Bsm[t*16+n] = __ldcg(&row[16+n]);
                Csm[t*16+n] = __ldcg(&row[32+n]);
                int ch = i >> 5, tt = i & 31;
                int tri = (b*DI + d0 + ch)*TT + tt;
                float dtv = __ldcg(&g_dtt[tri]);
                float xv  = __ldcg(&g_xct[tri]);
                dts[ch*32+tt] = dtv;
                ws [ch*32+tt] = dtv*xv;
                xs [ch*32+tt] = xv;
                zs [ch*32+tt] = __ldcg(&g_ztr[tri]);
                es [ch*32+tt] = __expf(dtv * A0s[ch]);
            }
            __syncthreads();
            int lane = tid & 31;
            int ch = (tid >> 5)*2 + (lane >> 4);
            int n = lane & 15;
            int d = d0 + ch;
            float An = -__expf(al_l[d*DS + n]);
            float A0 = A0s[ch];
            bool fast = fabsf(An - (float)(n+1)*A0) <= 1e-5f*fabsf(An) + 1e-7f;
            fast = __all_sync(0xffffffffu, fast);
            float Dd = dp_l[d];
            float h = 0.f;
            int np = n + 1;
            if (fast) {
                #pragma unroll 4
                for (int t = 0; t < TT; t++) {
                    float e1 = es[ch*32+t];
                    float p2 = e1*e1, p4 = p2*p2, p8 = p4*p4;
                    float a = 1.f;
                    if (np & 1)  a *= e1;
                    if (np & 2)  a *= p2;
                    if (np & 4)  a *= p4;
                    if (np & 8)  a *= p8;
                    if (np & 16) a *= p8*p8;
                    h = a*h + ws[ch*32+t]*Bsm[t*16+n];
                    float v = h*Csm[t*16+n];
                    v += __shfl_xor_sync(0xffffffffu, v, 8);
                    v += __shfl_xor_sync(0xffffffffu, v, 4);
                    v += __shfl_xor_sync(0xffffffffu, v, 2);
                    v += __shfl_xor_sync(0xffffffffu, v, 1);
                    if (n == 0) {
                        float zv = zs[ch*32+t];
                        float sz = zv / (1.f + __expf(-zv));
                        g_y[(b*TT+t)*DI + d] = (v + Dd*xs[ch*32+t]) * sz;
                    }
                }
            } else {
                #pragma unroll 4
                for (int t = 0; t < TT; t++) {
                    float a = __expf(dts[ch*32+t]*An);
                    h = a*h + ws[ch*32+t]*Bsm[t*16+n];
                    float v = h*Csm[t*16+n];
                    v += __shfl_xor_sync(0xffffffffu, v, 8);
                    v += __shfl_xor_sync(0xffffffffu, v, 4);
                    v += __shfl_xor_sync(0xffffffffu, v, 2);
                    v += __shfl_xor_sync(0xffffffffu, v, 1);
                    if (n == 0) {
                        float zv = zs[ch*32+t];
                        float sz = zv / (1.f + __expf(-zv));
                        g_y[(b*TT+t)*DI + d] = (v + Dd*xs[ch*32+t]) * sz;
                    }
                }
            }
        }
        bsync(b, gen);

        // -------- out_proj: 4 N-tiles x splitK8 = 32 units (1 per rank) --
        {
            int t = rank & 3;             // N tile
            int s = rank >> 2;            // split (0..7)
            gemm_tile32(g_y, opw_l, &g_outp[s][0], DM, DI,
                        b*TT, t*64, s*64, s*64+64, SMF);
        }
        bsync(b, gen);

        // -------- residual + LN (1 token per rank) -----------------------
        {
            float* red = SMF;
            int tok = b*TT + rank;
            int d = tid;
            size_t o = (size_t)tok*DM + d;
            float v = __ldcg(&g_feat[o]);
            #pragma unroll
            for (int sp = 0; sp < SPLIT_OUT; sp++) v += __ldcg(&g_outp[sp][o]);
            red[d] = v; __syncthreads();
            for (int off=128; off; off>>=1){ if (d<off) red[d]+=red[d+off]; __syncthreads(); }
            float mean = red[0]*(1.f/DM); __syncthreads();
            float dv = v-mean; red[d]=dv*dv; __syncthreads();
            for (int off=128; off; off>>=1){ if (d<off) red[d]+=red[d+off]; __syncthreads(); }
            float var = red[0]*(1.f/DM);
            g_feat[o] = dv*rsqrtf(var+1e-5f)*ng[d] + nb[d];
        }
        bsync(b, gen);
    }

    // ---------------- classifier on token 31 (rank 0 per batch) -----------
    if (rank == 0) {
        float* hs = SMF;
        int j = tid;
        const float* fr = g_feat + (size_t)(b*TT + 31)*DM;
        if (j < 128) {
            float acc = b1[j];
            const float* wr = w1 + j*DM;
            #pragma unroll 8
            for (int d = 0; d < DM; d++) acc += __ldcg(&fr[d])*wr[d];
            hs[j] = fmaxf(acc, 0.f);
        }
        __syncthreads();
        if (j < 2) {
            float o = b2[j];
            const float* w2r = w2 + j*128;
            #pragma unroll 8
            for (int k = 0; k < 128; k++) o += hs[k]*w2r[k];
            out[b*2 + j] = o;
        }
    }
}

// ---------------------------------------------------------------------------
extern "C" void kernel_launch(void* const* d_in, const int* in_sizes, int n_in,
                              void* d_out, int out_size)
{
    reset_bar<<<1, 256>>>();
    mega<<<NB*CPB, THREADS>>>(
        (const float*)d_in[0],  (const float*)d_in[1],  (const float*)d_in[2],
        (const float*)d_in[3],  (const float*)d_in[4],  (const float*)d_in[5],
        (const float*)d_in[6],  (const float*)d_in[7],  (const float*)d_in[8],
        (const float*)d_in[9],  (const float*)d_in[10], (const float*)d_in[11],
        (const float*)d_in[12], (const float*)d_in[13], (const float*)d_in[14],
        (const float*)d_in[15], (const float*)d_in[16], (const float*)d_in[17],
        (const float*)d_in[18], (const float*)d_in[19], (const float*)d_in[20],
        (const float*)d_in[21], (const float*)d_in[22], (const float*)d_in[23],
        (const float*)d_in[24], (const float*)d_in[25], (const float*)d_in[26],
        (float*)d_out);
}

// round 14
// speedup vs baseline: 1.3522x; 1.1693x over previous
#include <cuda_runtime.h>
#include <cuda_bf16.h>
#include <math.h>

// B=16, T=32 (early exit: only token 31 feeds classifier; all ops causal),
// DM=256, DI=512, DS=16, DR=16, DCONV=4, L=4.
// Multi-kernel pipeline (graph-captured): best proven version of each stage.

#define NB      16
#define TT      32
#define NTOK    (NB*TT)      // 512
#define DM      256
#define DI      512
#define DS      16
#define DR      16
#define NL      4
#define SPLIT_IN  2
#define SPLIT_OUT 8

// scratch (device globals; no allocation allowed)
__device__ __align__(16) float g_feat[NTOK*DM];
__device__ __align__(16) float g_xzp [SPLIT_IN][NTOK*2*DI];
__device__ __align__(16) float g_dbl [NTOK*48];
__device__ __align__(16) float g_xct [NB*DI*TT];
__device__ __align__(16) float g_ztr [NB*DI*TT];
__device__ __align__(16) float g_dtt [NB*DI*TT];
__device__ __align__(16) float g_y   [NTOK*DI];
__device__ __align__(16) float g_outp[SPLIT_OUT][NTOK*DM];

// ---------------------------------------------------------------------------
// featurize + token LN -> g_feat. One block per token (proven R1/R2).
// ---------------------------------------------------------------------------
__global__ void featurize(const float* __restrict__ x,
                          const float* __restrict__ ep,  const float* __restrict__ ef,
                          const float* __restrict__ ed,
                          const float* __restrict__ plw, const float* __restrict__ plb,
                          const float* __restrict__ piw, const float* __restrict__ pib,
                          const float* __restrict__ fw,  const float* __restrict__ fb,
                          const float* __restrict__ tg,  const float* __restrict__ tb,
                          float* __restrict__ feat)
{
    __shared__ float cat[136];
    __shared__ float red[DM];
    int tok = blockIdx.x;
    int b = tok >> 5, tl = tok & 31;
    const float* xr = x + (b*1024 + tl)*5;
    int d = threadIdx.x;
    if (d < 136) {
        float v;
        if (d < 32)       { int p = (int)xr[0]; p = min(max(p,0),255); v = ep[p*32 + d]; }
        else if (d < 64)  { v = xr[1]*plw[d-32] + plb[d-32]; }
        else if (d < 96)  { int f = (int)xr[2]; f = min(max(f,0),63);  v = ef[f*32 + (d-64)]; }
        else if (d < 128) { v = xr[3]*piw[d-96] + pib[d-96]; }
        else              { int dd = (int)xr[4]; dd = min(max(dd,0),1); v = ed[dd*8 + (d-128)]; }
        cat[d] = v;
    }
    __syncthreads();
    float acc = fb[d];
    const float* wrow = fw + d*136;
    #pragma unroll 8
    for (int j = 0; j < 136; j++) acc += cat[j]*wrow[j];
    red[d] = acc; __syncthreads();
    for (int off = 128; off; off >>= 1) { if (d < off) red[d] += red[d+off]; __syncthreads(); }
    float mean = red[0] * (1.f/DM); __syncthreads();
    float dv = acc - mean; red[d] = dv*dv; __syncthreads();
    for (int off = 128; off; off >>= 1) { if (d < off) red[d] += red[d+off]; __syncthreads(); }
    float var = red[0] * (1.f/DM);
    feat[tok*DM + d] = dv * rsqrtf(var + 1e-5f) * tg[d] + tb[d];
}

// ---------------------------------------------------------------------------
// Split-K SGEMM: Cp[z][M,N] = A[:, z*ks : (z+1)*ks] @ B^T slice.
// BM=BN=64, BK=16, 256 thr, 4x4 microtile (proven R2 body).
// grid: (N/64, M/64, S)
// ---------------------------------------------------------------------------
__global__ void gemm_tn_split(const float* __restrict__ A, const float* __restrict__ B,
                              float* __restrict__ Cp, int M, int N, int K, int ks)
{
    __shared__ __align__(16) float As[16][68];
    __shared__ __align__(16) float Bs[16][68];
    int bm = blockIdx.y*64, bn = blockIdx.x*64;
    int z  = blockIdx.z;
    int kbeg = z*ks, kend = kbeg + ks;
    float* C = Cp + (size_t)z*M*N;
    int tid = threadIdx.x;
    int lr = tid >> 2;
    int lk = (tid & 3) * 4;
    int ty = tid >> 4, tx = tid & 15;
    float acc[4][4] = {};
    for (int k0 = kbeg; k0 < kend; k0 += 16) {
        float4 av = *(const float4*)(A + (size_t)(bm+lr)*K + k0 + lk);
        float4 bv = *(const float4*)(B + (size_t)(bn+lr)*K + k0 + lk);
        As[lk+0][lr]=av.x; As[lk+1][lr]=av.y; As[lk+2][lr]=av.z; As[lk+3][lr]=av.w;
        Bs[lk+0][lr]=bv.x; Bs[lk+1][lr]=bv.y; Bs[lk+2][lr]=bv.z; Bs[lk+3][lr]=bv.w;
        __syncthreads();
        #pragma unroll
        for (int k = 0; k < 16; k++) {
            float4 a = *(const float4*)&As[k][ty*4];
            float4 bb = *(const float4*)&Bs[k][tx*4];
            float ar[4] = {a.x,a.y,a.z,a.w};
            float br[4] = {bb.x,bb.y,bb.z,bb.w};
            #pragma unroll
            for (int r = 0; r < 4; r++)
                #pragma unroll
                for (int c = 0; c < 4; c++)
                    acc[r][c] += ar[r]*br[c];
        }
        __syncthreads();
    }
    #pragma unroll
    for (int r = 0; r < 4; r++)
        *(float4*)(C + (size_t)(bm+ty*4+r)*N + bn + tx*4) =
            make_float4(acc[r][0],acc[r][1],acc[r][2],acc[r][3]);
}

// ---------------------------------------------------------------------------
// Fused: sum in_proj partials; causal conv(4)+SiLU; x_proj (48); softplus dt.
// Writes xc/z/dt in [b,d,t] layout. One block (512 thr) per token (proven R2
// body + proven R7 split-sum).
// ---------------------------------------------------------------------------
__global__ void fused_mid(const float* __restrict__ cw, const float* __restrict__ cb,
                          const float* __restrict__ xpw,
                          const float* __restrict__ dtw, const float* __restrict__ dtb,
                          float* __restrict__ xct, float* __restrict__ ztr,
                          float* __restrict__ dbl, float* __restrict__ dtt)
{
    __shared__ float xcs[DI];
    __shared__ float dbls[48];
    int tok = blockIdx.x;
    int b = tok >> 5, tl = tok & 31;
    int d = threadIdx.x;
    const float* xz0 = &g_xzp[0][0];
    const float* xz1 = &g_xzp[1][0];

    float acc = cb[d];
    #pragma unroll
    for (int k = 0; k < 4; k++) {
        int tt = tl - 3 + k;
        if (tt >= 0) {
            int off = (tok - 3 + k)*(2*DI) + d;
            acc += cw[d*4 + k] * (xz0[off] + xz1[off]);
        }
    }
    float s = acc / (1.f + __expf(-acc));   // SiLU
    xcs[d] = s;
    int tri = (b*DI + d)*TT + tl;
    xct[tri] = s;
    int zo = tok*(2*DI) + DI + d;
    ztr[tri] = xz0[zo] + xz1[zo];
    __syncthreads();

    int warp = d >> 5, lane = d & 31;
    #pragma unroll
    for (int i = 0; i < 3; i++) {
        int o = warp*3 + i;                 // 16 warps * 3 = 48 outputs
        const float* wr = xpw + o*DI;
        float p = 0.f;
        #pragma unroll
        for (int j = 0; j < 16; j++) p += xcs[j*32+lane]*wr[j*32+lane];
        #pragma unroll
        for (int off = 16; off; off >>= 1) p += __shfl_down_sync(0xffffffffu, p, off);
        if (lane == 0) { dbls[o] = p; dbl[tok*48 + o] = p; }
    }
    __syncthreads();

    float v = dtb[d];
    const float* dwr = dtw + d*DR;
    #pragma unroll
    for (int r = 0; r < DR; r++) v += dbls[r]*dwr[r];
    dtt[tri] = (v > 20.f) ? v : log1pf(__expf(v));   // softplus
}

// ---------------------------------------------------------------------------
// Selective scan: one block per (batch, 16-channel chunk); serial t,
// parallel (d,n); exp fast-path with generic fallback (proven R13 body).
// ---------------------------------------------------------------------------
__global__ void scan3(const float* __restrict__ dtt, const float* __restrict__ xct,
                      const float* __restrict__ ztr, const float* __restrict__ dbl,
                      const float* __restrict__ alog, const float* __restrict__ dp,
                      float* __restrict__ y)
{
    __shared__ float Bsm[512], Csm[512], ws[512], es[512];
    __shared__ float xs[512], zs[512], dts[512], A0s[16];
    int chunk = blockIdx.x;
    int b = chunk >> 5;
    int d0 = (chunk & 31) * 16;
    int tid = threadIdx.x;

    if (tid < 16) A0s[tid] = -__expf(alog[(d0+tid)*DS]);
    __syncthreads();
    #pragma unroll
    for (int i = tid; i < 512; i += 256) {
        int t = i >> 4, n = i & 15;
        const float* row = dbl + (b*TT + t)*48;
        Bsm[t*16+n] = row[16+n];
        Csm[t*16+n] = row[32+n];
        int ch = i >> 5, tt = i & 31;
        int tri = (b*DI + d0 + ch)*TT + tt;
        float dtv = dtt[tri];
        float xv  = xct[tri];
        dts[ch*32+tt] = dtv;
        ws [ch*32+tt] = dtv*xv;
        xs [ch*32+tt] = xv;
        zs [ch*32+tt] = ztr[tri];
        es [ch*32+tt] = __expf(dtv * A0s[ch]);
    }
    __syncthreads();
    int lane = tid & 31;
    int ch = (tid >> 5)*2 + (lane >> 4);
    int n = lane & 15;
    int d = d0 + ch;
    float An = -__expf(alog[d*DS + n]);
    float A0 = A0s[ch];
    bool fast = fabsf(An - (float)(n+1)*A0) <= 1e-5f*fabsf(An) + 1e-7f;
    fast = __all_sync(0xffffffffu, fast);
    float Dd = dp[d];
    float h = 0.f;
    int np = n + 1;
    if (fast) {
        #pragma unroll 4
        for (int t = 0; t < TT; t++) {
            float e1 = es[ch*32+t];
            float p2 = e1*e1, p4 = p2*p2, p8 = p4*p4;
            float a = 1.f;
            if (np & 1)  a *= e1;
            if (np & 2)  a *= p2;
            if (np & 4)  a *= p4;
            if (np & 8)  a *= p8;
            if (np & 16) a *= p8*p8;
            h = a*h + ws[ch*32+t]*Bsm[t*16+n];
            float v = h*Csm[t*16+n];
            v += __shfl_xor_sync(0xffffffffu, v, 8);
            v += __shfl_xor_sync(0xffffffffu, v, 4);
            v += __shfl_xor_sync(0xffffffffu, v, 2);
            v += __shfl_xor_sync(0xffffffffu, v, 1);
            if (n == 0) {
                float zv = zs[ch*32+t];
                float sz = zv / (1.f + __expf(-zv));
                y[(b*TT+t)*DI + d] = (v + Dd*xs[ch*32+t]) * sz;
            }
        }
    } else {
        #pragma unroll 4
        for (int t = 0; t < TT; t++) {
            float a = __expf(dts[ch*32+t]*An);
            h = a*h + ws[ch*32+t]*Bsm[t*16+n];
            float v = h*Csm[t*16+n];
            v += __shfl_xor_sync(0xffffffffu, v, 8);
            v += __shfl_xor_sync(0xffffffffu, v, 4);
            v += __shfl_xor_sync(0xffffffffu, v, 2);
            v += __shfl_xor_sync(0xffffffffu, v, 1);
            if (n == 0) {
                float zv = zs[ch*32+t];
                float sz = zv / (1.f + __expf(-zv));
                y[(b*TT+t)*DI + d] = (v + Dd*xs[ch*32+t]) * sz;
            }
        }
    }
}

// ---------------------------------------------------------------------------
// residual + sum of 8 out_proj partials + LayerNorm -> feat. One block/token.
// ---------------------------------------------------------------------------
__global__ void add_ln(float* __restrict__ feat,
                       const float* __restrict__ g, const float* __restrict__ b)
{
    __shared__ float red[DM];
    int tok = blockIdx.x, d = threadIdx.x;
    size_t o = (size_t)tok*DM + d;
    float v = feat[o];
    #pragma unroll
    for (int sp = 0; sp < SPLIT_OUT; sp++) v += g_outp[sp][o];
    red[d] = v; __syncthreads();
    for (int off = 128; off; off >>= 1) { if (d < off) red[d] += red[d+off]; __syncthreads(); }
    float mean = red[0] * (1.f/DM); __syncthreads();
    float dv = v - mean; red[d] = dv*dv; __syncthreads();
    for (int off = 128; off; off >>= 1) { if (d < off) red[d] += red[d+off]; __syncthreads(); }
    float var = red[0] * (1.f/DM);
    feat[o] = dv * rsqrtf(var + 1e-5f) * g[d] + b[d];
}

// ---------------------------------------------------------------------------
// Classifier on token 31 of each batch (proven).
// ---------------------------------------------------------------------------
__global__ void classifier(const float* __restrict__ feat,
                           const float* __restrict__ w1, const float* __restrict__ b1,
                           const float* __restrict__ w2, const float* __restrict__ b2,
                           float* __restrict__ out)
{
    __shared__ float hs[128];
    int b = blockIdx.x, j = threadIdx.x;
    const float* fr = feat + (b*TT + 31)*DM;
    float acc = b1[j];
    const float* wr = w1 + j*DM;
    #pragma unroll 8
    for (int d = 0; d < DM; d++) acc += fr[d]*wr[d];
    hs[j] = fmaxf(acc, 0.f);
    __syncthreads();
    if (j < 2) {
        float o = b2[j];
        const float* w2r = w2 + j*128;
        #pragma unroll 8
        for (int k = 0; k < 128; k++) o += hs[k]*w2r[k];
        out[b*2 + j] = o;
    }
}

// ---------------------------------------------------------------------------
static float* sym_addr(const void* sym) {
    void* p = nullptr;
    cudaGetSymbolAddress(&p, sym);
    return (float*)p;
}

extern "C" void kernel_launch(void* const* d_in, const int* in_sizes, int n_in,
                              void* d_out, int out_size)
{
    const float* x         = (const float*)d_in[0];
    const float* emb_proto = (const float*)d_in[1];
    const float* emb_flags = (const float*)d_in[2];
    const float* emb_dir   = (const float*)d_in[3];
    const float* plw       = (const float*)d_in[4];
    const float* plb       = (const float*)d_in[5];
    const float* piw       = (const float*)d_in[6];
    const float* pib       = (const float*)d_in[7];
    const float* fusion_w  = (const float*)d_in[8];
    const float* fusion_b  = (const float*)d_in[9];
    const float* tok_g     = (const float*)d_in[10];
    const float* tok_b     = (const float*)d_in[11];
    const float* norm_g    = (const float*)d_in[12];
    const float* norm_b    = (const float*)d_in[13];
    const float* in_proj_w = (const float*)d_in[14];
    const float* conv_w    = (const float*)d_in[15];
    const float* conv_b    = (const float*)d_in[16];
    const float* x_proj_w  = (const float*)d_in[17];
    const float* dt_w      = (const float*)d_in[18];
    const float* dt_b      = (const float*)d_in[19];
    const float* A_log     = (const float*)d_in[20];
    const float* D_param   = (const float*)d_in[21];
    const float* out_proj_w= (const float*)d_in[22];
    const float* cls_w1    = (const float*)d_in[23];
    const float* cls_b1    = (const float*)d_in[24];
    const float* cls_w2    = (const float*)d_in[25];
    const float* cls_b2    = (const float*)d_in[26];

    static float *feat=nullptr, *xzp, *dbl, *xct, *ztr, *dtt, *y, *outp;
    if (!feat) {
        feat = sym_addr(g_feat); xzp = sym_addr(g_xzp); dbl = sym_addr(g_dbl);
        xct = sym_addr(g_xct);   ztr = sym_addr(g_ztr); dtt = sym_addr(g_dtt);
        y = sym_addr(g_y);       outp = sym_addr(g_outp);
    }

    featurize<<<NTOK, DM>>>(x, emb_proto, emb_flags, emb_dir,
                            plw, plb, piw, pib,
                            fusion_w, fusion_b, tok_g, tok_b, feat);

    for (int l = 0; l < NL; l++) {
        // in_proj: M=512, N=1024, K=256, split-K=2 -> 256 blocks
        gemm_tn_split<<<dim3((2*DI)/64, NTOK/64, SPLIT_IN), 256>>>(
            feat, in_proj_w + (size_t)l*2*DI*DM, xzp, NTOK, 2*DI, DM, DM/SPLIT_IN);

        fused_mid<<<NTOK, DI>>>(conv_w + (size_t)l*DI*4, conv_b + (size_t)l*DI,
                                x_proj_w + (size_t)l*48*DI,
                                dt_w + (size_t)l*DI*DR, dt_b + (size_t)l*DI,
                                xct, ztr, dbl, dtt);

        scan3<<<NB*32, 256>>>(dtt, xct, ztr, dbl,
                              A_log + (size_t)l*DI*DS,
                              D_param + (size_t)l*DI, y);

        // out_proj: M=512, N=256, K=512, split-K=8 -> 256 blocks
        gemm_tn_split<<<dim3(DM/64, NTOK/64, SPLIT_OUT), 256>>>(
            y, out_proj_w + (size_t)l*DM*DI, outp, NTOK, DM, DI, DI/SPLIT_OUT);

        add_ln<<<NTOK, DM>>>(feat, norm_g, norm_b);
    }

    classifier<<<NB, 128>>>(feat, cls_w1, cls_b1, cls_w2, cls_b2, (float*)d_out);
}

// round 15
// speedup vs baseline: 1.4364x; 1.0623x over previous
#include <cuda_runtime.h>
#include <cuda_bf16.h>
#include <math.h>

// B=16, T=32 (early exit: only token 31 feeds classifier; all ops causal),
// DM=256, DI=512, DS=16, DR=16, DCONV=4, L=4.
// Multi-kernel pipeline (graph-captured). This round: natural-layout
// activations (coalesced mid writes), lean scan body (generic exp only),
// simplified split-K.

#define NB      16
#define TT      32
#define NTOK    (NB*TT)      // 512
#define DM      256
#define DI      512
#define DS      16
#define DR      16
#define NL      4
#define SPLIT_OUT 4

// scratch (device globals; no allocation allowed)
__device__ __align__(16) float g_feat[NTOK*DM];
__device__ __align__(16) float g_xz  [NTOK*2*DI];
__device__ __align__(16) float g_dbl [NTOK*48];
__device__ __align__(16) float g_xcn [NTOK*DI];   // xc, [tok,d]
__device__ __align__(16) float g_zn  [NTOK*DI];   // z,  [tok,d]
__device__ __align__(16) float g_dtn [NTOK*DI];   // dt, [tok,d]
__device__ __align__(16) float g_y   [NTOK*DI];
__device__ __align__(16) float g_outp[SPLIT_OUT][NTOK*DM];

// ---------------------------------------------------------------------------
// featurize + token LN -> g_feat. One block per token.
// ---------------------------------------------------------------------------
__global__ void featurize(const float* __restrict__ x,
                          const float* __restrict__ ep,  const float* __restrict__ ef,
                          const float* __restrict__ ed,
                          const float* __restrict__ plw, const float* __restrict__ plb,
                          const float* __restrict__ piw, const float* __restrict__ pib,
                          const float* __restrict__ fw,  const float* __restrict__ fb,
                          const float* __restrict__ tg,  const float* __restrict__ tb,
                          float* __restrict__ feat)
{
    __shared__ float cat[136];
    __shared__ float red[DM];
    int tok = blockIdx.x;
    int b = tok >> 5, tl = tok & 31;
    const float* xr = x + (b*1024 + tl)*5;
    int d = threadIdx.x;
    if (d < 136) {
        float v;
        if (d < 32)       { int p = (int)xr[0]; p = min(max(p,0),255); v = ep[p*32 + d]; }
        else if (d < 64)  { v = xr[1]*plw[d-32] + plb[d-32]; }
        else if (d < 96)  { int f = (int)xr[2]; f = min(max(f,0),63);  v = ef[f*32 + (d-64)]; }
        else if (d < 128) { v = xr[3]*piw[d-96] + pib[d-96]; }
        else              { int dd = (int)xr[4]; dd = min(max(dd,0),1); v = ed[dd*8 + (d-128)]; }
        cat[d] = v;
    }
    __syncthreads();
    float acc = fb[d];
    const float* wrow = fw + d*136;
    #pragma unroll 8
    for (int j = 0; j < 136; j++) acc += cat[j]*wrow[j];
    red[d] = acc; __syncthreads();
    for (int off = 128; off; off >>= 1) { if (d < off) red[d] += red[d+off]; __syncthreads(); }
    float mean = red[0] * (1.f/DM); __syncthreads();
    float dv = acc - mean; red[d] = dv*dv; __syncthreads();
    for (int off = 128; off; off >>= 1) { if (d < off) red[d] += red[d+off]; __syncthreads(); }
    float var = red[0] * (1.f/DM);
    feat[tok*DM + d] = dv * rsqrtf(var + 1e-5f) * tg[d] + tb[d];
}

// ---------------------------------------------------------------------------
// Split-K SGEMM: Cp[z][M,N] = A[:, z*ks:(z+1)*ks] @ B^T slice.
// BM=BN=64, BK=16, 256 thr, 4x4 microtile. grid (N/64, M/64, S).
// ---------------------------------------------------------------------------
__global__ void gemm_tn_split(const float* __restrict__ A, const float* __restrict__ B,
                              float* __restrict__ Cp, int M, int N, int K, int ks)
{
    __shared__ __align__(16) float As[16][68];
    __shared__ __align__(16) float Bs[16][68];
    int bm = blockIdx.y*64, bn = blockIdx.x*64;
    int z  = blockIdx.z;
    int kbeg = z*ks, kend = kbeg + ks;
    float* C = Cp + (size_t)z*M*N;
    int tid = threadIdx.x;
    int lr = tid >> 2;
    int lk = (tid & 3) * 4;
    int ty = tid >> 4, tx = tid & 15;
    float acc[4][4] = {};
    for (int k0 = kbeg; k0 < kend; k0 += 16) {
        float4 av = *(const float4*)(A + (size_t)(bm+lr)*K + k0 + lk);
        float4 bv = *(const float4*)(B + (size_t)(bn+lr)*K + k0 + lk);
        As[lk+0][lr]=av.x; As[lk+1][lr]=av.y; As[lk+2][lr]=av.z; As[lk+3][lr]=av.w;
        Bs[lk+0][lr]=bv.x; Bs[lk+1][lr]=bv.y; Bs[lk+2][lr]=bv.z; Bs[lk+3][lr]=bv.w;
        __syncthreads();
        #pragma unroll
        for (int k = 0; k < 16; k++) {
            float4 a = *(const float4*)&As[k][ty*4];
            float4 bb = *(const float4*)&Bs[k][tx*4];
            float ar[4] = {a.x,a.y,a.z,a.w};
            float br[4] = {bb.x,bb.y,bb.z,bb.w};
            #pragma unroll
            for (int r = 0; r < 4; r++)
                #pragma unroll
                for (int c = 0; c < 4; c++)
                    acc[r][c] += ar[r]*br[c];
        }
        __syncthreads();
    }
    #pragma unroll
    for (int r = 0; r < 4; r++)
        *(float4*)(C + (size_t)(bm+ty*4+r)*N + bn + tx*4) =
            make_float4(acc[r][0],acc[r][1],acc[r][2],acc[r][3]);
}

// ---------------------------------------------------------------------------
// Fused: causal conv(4)+SiLU; x_proj (48); softplus dt. Natural [tok,d]
// outputs (coalesced). One block (512 thr) per token.
// ---------------------------------------------------------------------------
__global__ void fused_mid(const float* __restrict__ cw, const float* __restrict__ cb,
                          const float* __restrict__ xpw,
                          const float* __restrict__ dtw, const float* __restrict__ dtb,
                          float* __restrict__ xcn, float* __restrict__ zn,
                          float* __restrict__ dbl, float* __restrict__ dtn)
{
    __shared__ float xcs[DI];
    __shared__ float dbls[48];
    int tok = blockIdx.x;
    int tl = tok & 31;
    int d = threadIdx.x;

    float acc = cb[d];
    #pragma unroll
    for (int k = 0; k < 4; k++) {
        int tt = tl - 3 + k;
        if (tt >= 0)
            acc += cw[d*4 + k] * g_xz[(size_t)(tok - 3 + k)*(2*DI) + d];
    }
    float s = acc / (1.f + __expf(-acc));   // SiLU
    xcs[d] = s;
    xcn[tok*DI + d] = s;
    zn [tok*DI + d] = g_xz[(size_t)tok*(2*DI) + DI + d];
    __syncthreads();

    int warp = d >> 5, lane = d & 31;
    #pragma unroll
    for (int i = 0; i < 3; i++) {
        int o = warp*3 + i;                 // 16 warps * 3 = 48 outputs
        const float* wr = xpw + o*DI;
        float p = 0.f;
        #pragma unroll
        for (int j = 0; j < 16; j++) p += xcs[j*32+lane]*wr[j*32+lane];
        #pragma unroll
        for (int off = 16; off; off >>= 1) p += __shfl_down_sync(0xffffffffu, p, off);
        if (lane == 0) { dbls[o] = p; dbl[tok*48 + o] = p; }
    }
    __syncthreads();

    float v = dtb[d];
    const float* dwr = dtw + d*DR;
    #pragma unroll
    for (int r = 0; r < DR; r++) v += dbls[r]*dwr[r];
    dtn[tok*DI + d] = (v > 20.f) ? v : log1pf(__expf(v));   // softplus
}

// ---------------------------------------------------------------------------
// Selective scan: one block per (batch, 16-channel chunk); serial t,
// parallel (d,n). Lean body: generic exp only. Natural-layout inputs,
// conflict-free transposed smem staging (stride 33).
// ---------------------------------------------------------------------------
__global__ void scan3(const float* __restrict__ dtn, const float* __restrict__ xcn,
                      const float* __restrict__ zn, const float* __restrict__ dbl,
                      const float* __restrict__ alog, const float* __restrict__ dp,
                      float* __restrict__ y)
{
    __shared__ float Bsm[512], Csm[512];
    __shared__ float dts[16*33], ws[16*33], xs[16*33], zs[16*33];
    int chunk = blockIdx.x;
    int b = chunk >> 5;
    int d0 = (chunk & 31) * 16;
    int tid = threadIdx.x;

    // stage: i -> (t = i>>4, c = i&15); LDG coalesced 64B; smem stride 33
    #pragma unroll
    for (int i = tid; i < 512; i += 256) {
        int t = i >> 4, c = i & 15;
        const float* row = dbl + (b*TT + t)*48;
        Bsm[t*16+c] = row[16+c];
        Csm[t*16+c] = row[32+c];
        size_t o = (size_t)(b*TT + t)*DI + d0 + c;
        float dtv = dtn[o];
        float xv  = xcn[o];
        dts[c*33+t] = dtv;
        ws [c*33+t] = dtv*xv;
        xs [c*33+t] = xv;
        zs [c*33+t] = zn[o];
    }
    __syncthreads();

    int lane = tid & 31;
    int ch = (tid >> 5)*2 + (lane >> 4);    // 0..15
    int n = lane & 15;
    int d = d0 + ch;
    float An = -__expf(alog[d*DS + n]);
    float Dd = dp[d];
    float h = 0.f;
    #pragma unroll 4
    for (int t = 0; t < TT; t++) {
        float a = __expf(dts[ch*33+t]*An);
        h = a*h + ws[ch*33+t]*Bsm[t*16+n];
        float v = h*Csm[t*16+n];
        v += __shfl_xor_sync(0xffffffffu, v, 8);
        v += __shfl_xor_sync(0xffffffffu, v, 4);
        v += __shfl_xor_sync(0xffffffffu, v, 2);
        v += __shfl_xor_sync(0xffffffffu, v, 1);
        if (n == 0) {
            float zv = zs[ch*33+t];
            float sz = zv / (1.f + __expf(-zv));
            y[(size_t)(b*TT+t)*DI + d] = (v + Dd*xs[ch*33+t]) * sz;
        }
    }
}

// ---------------------------------------------------------------------------
// residual + sum of 4 out_proj partials + LayerNorm -> feat. One block/token.
// ---------------------------------------------------------------------------
__global__ void add_ln(float* __restrict__ feat,
                       const float* __restrict__ g, const float* __restrict__ b)
{
    __shared__ float red[DM];
    int tok = blockIdx.x, d = threadIdx.x;
    size_t o = (size_t)tok*DM + d;
    float v = feat[o] + g_outp[0][o] + g_outp[1][o] + g_outp[2][o] + g_outp[3][o];
    red[d] = v; __syncthreads();
    for (int off = 128; off; off >>= 1) { if (d < off) red[d] += red[d+off]; __syncthreads(); }
    float mean = red[0] * (1.f/DM); __syncthreads();
    float dv = v - mean; red[d] = dv*dv; __syncthreads();
    for (int off = 128; off; off >>= 1) { if (d < off) red[d] += red[d+off]; __syncthreads(); }
    float var = red[0] * (1.f/DM);
    feat[o] = dv * rsqrtf(var + 1e-5f) * g[d] + b[d];
}

// ---------------------------------------------------------------------------
// Classifier on token 31 of each batch.
// ---------------------------------------------------------------------------
__global__ void classifier(const float* __restrict__ feat,
                           const float* __restrict__ w1, const float* __restrict__ b1,
                           const float* __restrict__ w2, const float* __restrict__ b2,
                           float* __restrict__ out)
{
    __shared__ float hs[128];
    int b = blockIdx.x, j = threadIdx.x;
    const float* fr = feat + (b*TT + 31)*DM;
    float acc = b1[j];
    const float* wr = w1 + j*DM;
    #pragma unroll 8
    for (int d = 0; d < DM; d++) acc += fr[d]*wr[d];
    hs[j] = fmaxf(acc, 0.f);
    __syncthreads();
    if (j < 2) {
        float o = b2[j];
        const float* w2r = w2 + j*128;
        #pragma unroll 8
        for (int k = 0; k < 128; k++) o += hs[k]*w2r[k];
        out[b*2 + j] = o;
    }
}

// ---------------------------------------------------------------------------
static float* sym_addr(const void* sym) {
    void* p = nullptr;
    cudaGetSymbolAddress(&p, sym);
    return (float*)p;
}

extern "C" void kernel_launch(void* const* d_in, const int* in_sizes, int n_in,
                              void* d_out, int out_size)
{
    const float* x         = (const float*)d_in[0];
    const float* emb_proto = (const float*)d_in[1];
    const float* emb_flags = (const float*)d_in[2];
    const float* emb_dir   = (const float*)d_in[3];
    const float* plw       = (const float*)d_in[4];
    const float* plb       = (const float*)d_in[5];
    const float* piw       = (const float*)d_in[6];
    const float* pib       = (const float*)d_in[7];
    const float* fusion_w  = (const float*)d_in[8];
    const float* fusion_b  = (const float*)d_in[9];
    const float* tok_g     = (const float*)d_in[10];
    const float* tok_b     = (const float*)d_in[11];
    const float* norm_g    = (const float*)d_in[12];
    const float* norm_b    = (const float*)d_in[13];
    const float* in_proj_w = (const float*)d_in[14];
    const float* conv_w    = (const float*)d_in[15];
    const float* conv_b    = (const float*)d_in[16];
    const float* x_proj_w  = (const float*)d_in[17];
    const float* dt_w      = (const float*)d_in[18];
    const float* dt_b      = (const float*)d_in[19];
    const float* A_log     = (const float*)d_in[20];
    const float* D_param   = (const float*)d_in[21];
    const float* out_proj_w= (const float*)d_in[22];
    const float* cls_w1    = (const float*)d_in[23];
    const float* cls_b1    = (const float*)d_in[24];
    const float* cls_w2    = (const float*)d_in[25];
    const float* cls_b2    = (const float*)d_in[26];

    static float *feat=nullptr, *xz, *dbl, *xcn, *zn, *dtn, *y, *outp;
    if (!feat) {
        feat = sym_addr(g_feat); xz = sym_addr(g_xz); dbl = sym_addr(g_dbl);
        xcn = sym_addr(g_xcn);   zn = sym_addr(g_zn); dtn = sym_addr(g_dtn);
        y = sym_addr(g_y);       outp = sym_addr(g_outp);
    }

    featurize<<<NTOK, DM>>>(x, emb_proto, emb_flags, emb_dir,
                            plw, plb, piw, pib,
                            fusion_w, fusion_b, tok_g, tok_b, feat);

    for (int l = 0; l < NL; l++) {
        // in_proj: M=512, N=1024, K=256, no split -> 128 blocks
        gemm_tn_split<<<dim3((2*DI)/64, NTOK/64, 1), 256>>>(
            feat, in_proj_w + (size_t)l*2*DI*DM, xz, NTOK, 2*DI, DM, DM);

        fused_mid<<<NTOK, DI>>>(conv_w + (size_t)l*DI*4, conv_b + (size_t)l*DI,
                                x_proj_w + (size_t)l*48*DI,
                                dt_w + (size_t)l*DI*DR, dt_b + (size_t)l*DI,
                                xcn, zn, dbl, dtn);

        scan3<<<NB*32, 256>>>(dtn, xcn, zn, dbl,
                              A_log + (size_t)l*DI*DS,
                              D_param + (size_t)l*DI, y);

        // out_proj: M=512, N=256, K=512, split-K=4 -> 128 blocks
        gemm_tn_split<<<dim3(DM/64, NTOK/64, SPLIT_OUT), 256>>>(
            y, out_proj_w + (size_t)l*DM*DI, outp, NTOK, DM, DI, DI/SPLIT_OUT);

        add_ln<<<NTOK, DM>>>(feat, norm_g, norm_b);
    }

    classifier<<<NB, 128>>>(feat, cls_w1, cls_b1, cls_w2, cls_b2, (float*)d_out);
}

// round 16
// speedup vs baseline: 1.5270x; 1.0631x over previous
#include <cuda_runtime.h>
#include <cuda_bf16.h>
#include <math.h>

// B=16, T=32 (early exit: only token 31 feeds classifier; all ops causal),
// DM=256, DI=512, DS=16, DR=16, DCONV=4, L=4.
// Multi-kernel pipeline (graph-captured). This round: scan float2-packed
// smem (half the LDS), in_proj split-K=2 for chip fill.

#define NB      16
#define TT      32
#define NTOK    (NB*TT)      // 512
#define DM      256
#define DI      512
#define DS      16
#define DR      16
#define NL      4
#define SPLIT_IN  2
#define SPLIT_OUT 4

// scratch (device globals; no allocation allowed)
__device__ __align__(16) float g_feat[NTOK*DM];
__device__ __align__(16) float g_xzp [SPLIT_IN][NTOK*2*DI];
__device__ __align__(16) float g_dbl [NTOK*48];
__device__ __align__(16) float g_xcn [NTOK*DI];   // xc, [tok,d]
__device__ __align__(16) float g_zn  [NTOK*DI];   // z,  [tok,d]
__device__ __align__(16) float g_dtn [NTOK*DI];   // dt, [tok,d]
__device__ __align__(16) float g_y   [NTOK*DI];
__device__ __align__(16) float g_outp[SPLIT_OUT][NTOK*DM];

// ---------------------------------------------------------------------------
// featurize + token LN -> g_feat. One block per token.
// ---------------------------------------------------------------------------
__global__ void featurize(const float* __restrict__ x,
                          const float* __restrict__ ep,  const float* __restrict__ ef,
                          const float* __restrict__ ed,
                          const float* __restrict__ plw, const float* __restrict__ plb,
                          const float* __restrict__ piw, const float* __restrict__ pib,
                          const float* __restrict__ fw,  const float* __restrict__ fb,
                          const float* __restrict__ tg,  const float* __restrict__ tb,
                          float* __restrict__ feat)
{
    __shared__ float cat[136];
    __shared__ float red[DM];
    int tok = blockIdx.x;
    int b = tok >> 5, tl = tok & 31;
    const float* xr = x + (b*1024 + tl)*5;
    int d = threadIdx.x;
    if (d < 136) {
        float v;
        if (d < 32)       { int p = (int)xr[0]; p = min(max(p,0),255); v = ep[p*32 + d]; }
        else if (d < 64)  { v = xr[1]*plw[d-32] + plb[d-32]; }
        else if (d < 96)  { int f = (int)xr[2]; f = min(max(f,0),63);  v = ef[f*32 + (d-64)]; }
        else if (d < 128) { v = xr[3]*piw[d-96] + pib[d-96]; }
        else              { int dd = (int)xr[4]; dd = min(max(dd,0),1); v = ed[dd*8 + (d-128)]; }
        cat[d] = v;
    }
    __syncthreads();
    float acc = fb[d];
    const float* wrow = fw + d*136;
    #pragma unroll 8
    for (int j = 0; j < 136; j++) acc += cat[j]*wrow[j];
    red[d] = acc; __syncthreads();
    for (int off = 128; off; off >>= 1) { if (d < off) red[d] += red[d+off]; __syncthreads(); }
    float mean = red[0] * (1.f/DM); __syncthreads();
    float dv = acc - mean; red[d] = dv*dv; __syncthreads();
    for (int off = 128; off; off >>= 1) { if (d < off) red[d] += red[d+off]; __syncthreads(); }
    float var = red[0] * (1.f/DM);
    feat[tok*DM + d] = dv * rsqrtf(var + 1e-5f) * tg[d] + tb[d];
}

// ---------------------------------------------------------------------------
// Split-K SGEMM: Cp[z][M,N] = A[:, z*ks:(z+1)*ks] @ B^T slice.
// BM=BN=64, BK=16, 256 thr, 4x4 microtile. grid (N/64, M/64, S).
// ---------------------------------------------------------------------------
__global__ void gemm_tn_split(const float* __restrict__ A, const float* __restrict__ B,
                              float* __restrict__ Cp, int M, int N, int K, int ks)
{
    __shared__ __align__(16) float As[16][68];
    __shared__ __align__(16) float Bs[16][68];
    int bm = blockIdx.y*64, bn = blockIdx.x*64;
    int z  = blockIdx.z;
    int kbeg = z*ks, kend = kbeg + ks;
    float* C = Cp + (size_t)z*M*N;
    int tid = threadIdx.x;
    int lr = tid >> 2;
    int lk = (tid & 3) * 4;
    int ty = tid >> 4, tx = tid & 15;
    float acc[4][4] = {};
    for (int k0 = kbeg; k0 < kend; k0 += 16) {
        float4 av = *(const float4*)(A + (size_t)(bm+lr)*K + k0 + lk);
        float4 bv = *(const float4*)(B + (size_t)(bn+lr)*K + k0 + lk);
        As[lk+0][lr]=av.x; As[lk+1][lr]=av.y; As[lk+2][lr]=av.z; As[lk+3][lr]=av.w;
        Bs[lk+0][lr]=bv.x; Bs[lk+1][lr]=bv.y; Bs[lk+2][lr]=bv.z; Bs[lk+3][lr]=bv.w;
        __syncthreads();
        #pragma unroll
        for (int k = 0; k < 16; k++) {
            float4 a = *(const float4*)&As[k][ty*4];
            float4 bb = *(const float4*)&Bs[k][tx*4];
            float ar[4] = {a.x,a.y,a.z,a.w};
            float br[4] = {bb.x,bb.y,bb.z,bb.w};
            #pragma unroll
            for (int r = 0; r < 4; r++)
                #pragma unroll
                for (int c = 0; c < 4; c++)
                    acc[r][c] += ar[r]*br[c];
        }
        __syncthreads();
    }
    #pragma unroll
    for (int r = 0; r < 4; r++)
        *(float4*)(C + (size_t)(bm+ty*4+r)*N + bn + tx*4) =
            make_float4(acc[r][0],acc[r][1],acc[r][2],acc[r][3]);
}

// ---------------------------------------------------------------------------
// Fused: sum in_proj partials; causal conv(4)+SiLU; x_proj (48); softplus dt.
// Natural [tok,d] outputs. One block (512 thr) per token.
// ---------------------------------------------------------------------------
__global__ void fused_mid(const float* __restrict__ cw, const float* __restrict__ cb,
                          const float* __restrict__ xpw,
                          const float* __restrict__ dtw, const float* __restrict__ dtb,
                          float* __restrict__ xcn, float* __restrict__ zn,
                          float* __restrict__ dbl, float* __restrict__ dtn)
{
    __shared__ float xcs[DI];
    __shared__ float dbls[48];
    int tok = blockIdx.x;
    int tl = tok & 31;
    int d = threadIdx.x;
    const float* xz0 = &g_xzp[0][0];
    const float* xz1 = &g_xzp[1][0];

    float acc = cb[d];
    #pragma unroll
    for (int k = 0; k < 4; k++) {
        int tt = tl - 3 + k;
        if (tt >= 0) {
            size_t off = (size_t)(tok - 3 + k)*(2*DI) + d;
            acc += cw[d*4 + k] * (xz0[off] + xz1[off]);
        }
    }
    float s = acc / (1.f + __expf(-acc));   // SiLU
    xcs[d] = s;
    xcn[tok*DI + d] = s;
    size_t zo = (size_t)tok*(2*DI) + DI + d;
    zn[tok*DI + d] = xz0[zo] + xz1[zo];
    __syncthreads();

    int warp = d >> 5, lane = d & 31;
    #pragma unroll
    for (int i = 0; i < 3; i++) {
        int o = warp*3 + i;                 // 16 warps * 3 = 48 outputs
        const float* wr = xpw + o*DI;
        float p = 0.f;
        #pragma unroll
        for (int j = 0; j < 16; j++) p += xcs[j*32+lane]*wr[j*32+lane];
        #pragma unroll
        for (int off = 16; off; off >>= 1) p += __shfl_down_sync(0xffffffffu, p, off);
        if (lane == 0) { dbls[o] = p; dbl[tok*48 + o] = p; }
    }
    __syncthreads();

    float v = dtb[d];
    const float* dwr = dtw + d*DR;
    #pragma unroll
    for (int r = 0; r < DR; r++) v += dbls[r]*dwr[r];
    dtn[tok*DI + d] = (v > 20.f) ? v : log1pf(__expf(v));   // softplus
}

// ---------------------------------------------------------------------------
// Selective scan: one block per (batch, 16-channel chunk); serial t,
// parallel (d,n). float2-packed smem: (dt,w) and (z, D*x) -> half the LDS.
// ---------------------------------------------------------------------------
__global__ void scan3(const float* __restrict__ dtn, const float* __restrict__ xcn,
                      const float* __restrict__ zn, const float* __restrict__ dbl,
                      const float* __restrict__ alog, const float* __restrict__ dp,
                      float* __restrict__ y)
{
    __shared__ float Bsm[512], Csm[512];
    __shared__ __align__(8) float2 dw2[16*33];   // (dt, dt*xc)
    __shared__ __align__(8) float2 zx2[16*33];   // (z, D*xc)
    int chunk = blockIdx.x;
    int b = chunk >> 5;
    int d0 = (chunk & 31) * 16;
    int tid = threadIdx.x;

    #pragma unroll
    for (int i = tid; i < 512; i += 256) {
        int t = i >> 4, c = i & 15;
        const float* row = dbl + (b*TT + t)*48;
        Bsm[t*16+c] = row[16+c];
        Csm[t*16+c] = row[32+c];
        size_t o = (size_t)(b*TT + t)*DI + d0 + c;
        float dtv = dtn[o];
        float xv  = xcn[o];
        dw2[c*33+t] = make_float2(dtv, dtv*xv);
        zx2[c*33+t] = make_float2(zn[o], dp[d0+c]*xv);
    }
    __syncthreads();

    int lane = tid & 31;
    int ch = (tid >> 5)*2 + (lane >> 4);    // 0..15
    int n = lane & 15;
    int d = d0 + ch;
    float An = -__expf(alog[d*DS + n]);
    float h = 0.f;
    #pragma unroll 4
    for (int t = 0; t < TT; t++) {
        float2 dw = dw2[ch*33+t];
        float a = __expf(dw.x*An);
        h = a*h + dw.y*Bsm[t*16+n];
        float v = h*Csm[t*16+n];
        v += __shfl_xor_sync(0xffffffffu, v, 8);
        v += __shfl_xor_sync(0xffffffffu, v, 4);
        v += __shfl_xor_sync(0xffffffffu, v, 2);
        v += __shfl_xor_sync(0xffffffffu, v, 1);
        if (n == 0) {
            float2 zx = zx2[ch*33+t];
            float sz = zx.x / (1.f + __expf(-zx.x));
            y[(size_t)(b*TT+t)*DI + d] = (v + zx.y) * sz;
        }
    }
}

// ---------------------------------------------------------------------------
// residual + sum of 4 out_proj partials + LayerNorm -> feat. One block/token.
// ---------------------------------------------------------------------------
__global__ void add_ln(float* __restrict__ feat,
                       const float* __restrict__ g, const float* __restrict__ b)
{
    __shared__ float red[DM];
    int tok = blockIdx.x, d = threadIdx.x;
    size_t o = (size_t)tok*DM + d;
    float v = feat[o] + g_outp[0][o] + g_outp[1][o] + g_outp[2][o] + g_outp[3][o];
    red[d] = v; __syncthreads();
    for (int off = 128; off; off >>= 1) { if (d < off) red[d] += red[d+off]; __syncthreads(); }
    float mean = red[0] * (1.f/DM); __syncthreads();
    float dv = v - mean; red[d] = dv*dv; __syncthreads();
    for (int off = 128; off; off >>= 1) { if (d < off) red[d] += red[d+off]; __syncthreads(); }
    float var = red[0] * (1.f/DM);
    feat[o] = dv * rsqrtf(var + 1e-5f) * g[d] + b[d];
}

// ---------------------------------------------------------------------------
// Classifier on token 31 of each batch.
// ---------------------------------------------------------------------------
__global__ void classifier(const float* __restrict__ feat,
                           const float* __restrict__ w1, const float* __restrict__ b1,
                           const float* __restrict__ w2, const float* __restrict__ b2,
                           float* __restrict__ out)
{
    __shared__ float hs[128];
    int b = blockIdx.x, j = threadIdx.x;
    const float* fr = feat + (b*TT + 31)*DM;
    float acc = b1[j];
    const float* wr = w1 + j*DM;
    #pragma unroll 8
    for (int d = 0; d < DM; d++) acc += fr[d]*wr[d];
    hs[j] = fmaxf(acc, 0.f);
    __syncthreads();
    if (j < 2) {
        float o = b2[j];
        const float* w2r = w2 + j*128;
        #pragma unroll 8
        for (int k = 0; k < 128; k++) o += hs[k]*w2r[k];
        out[b*2 + j] = o;
    }
}

// ---------------------------------------------------------------------------
static float* sym_addr(const void* sym) {
    void* p = nullptr;
    cudaGetSymbolAddress(&p, sym);
    return (float*)p;
}

extern "C" void kernel_launch(void* const* d_in, const int* in_sizes, int n_in,
                              void* d_out, int out_size)
{
    const float* x         = (const float*)d_in[0];
    const float* emb_proto = (const float*)d_in[1];
    const float* emb_flags = (const float*)d_in[2];
    const float* emb_dir   = (const float*)d_in[3];
    const float* plw       = (const float*)d_in[4];
    const float* plb       = (const float*)d_in[5];
    const float* piw       = (const float*)d_in[6];
    const float* pib       = (const float*)d_in[7];
    const float* fusion_w  = (const float*)d_in[8];
    const float* fusion_b  = (const float*)d_in[9];
    const float* tok_g     = (const float*)d_in[10];
    const float* tok_b     = (const float*)d_in[11];
    const float* norm_g    = (const float*)d_in[12];
    const float* norm_b    = (const float*)d_in[13];
    const float* in_proj_w = (const float*)d_in[14];
    const float* conv_w    = (const float*)d_in[15];
    const float* conv_b    = (const float*)d_in[16];
    const float* x_proj_w  = (const float*)d_in[17];
    const float* dt_w      = (const float*)d_in[18];
    const float* dt_b      = (const float*)d_in[19];
    const float* A_log     = (const float*)d_in[20];
    const float* D_param   = (const float*)d_in[21];
    const float* out_proj_w= (const float*)d_in[22];
    const float* cls_w1    = (const float*)d_in[23];
    const float* cls_b1    = (const float*)d_in[24];
    const float* cls_w2    = (const float*)d_in[25];
    const float* cls_b2    = (const float*)d_in[26];

    static float *feat=nullptr, *xzp, *dbl, *xcn, *zn, *dtn, *y, *outp;
    if (!feat) {
        feat = sym_addr(g_feat); xzp = sym_addr(g_xzp); dbl = sym_addr(g_dbl);
        xcn = sym_addr(g_xcn);   zn = sym_addr(g_zn); dtn = sym_addr(g_dtn);
        y = sym_addr(g_y);       outp = sym_addr(g_outp);
    }

    featurize<<<NTOK, DM>>>(x, emb_proto, emb_flags, emb_dir,
                            plw, plb, piw, pib,
                            fusion_w, fusion_b, tok_g, tok_b, feat);

    for (int l = 0; l < NL; l++) {
        // in_proj: M=512, N=1024, K=256, split-K=2 -> 256 blocks
        gemm_tn_split<<<dim3((2*DI)/64, NTOK/64, SPLIT_IN), 256>>>(
            feat, in_proj_w + (size_t)l*2*DI*DM, xzp, NTOK, 2*DI, DM, DM/SPLIT_IN);

        fused_mid<<<NTOK, DI>>>(conv_w + (size_t)l*DI*4, conv_b + (size_t)l*DI,
                                x_proj_w + (size_t)l*48*DI,
                                dt_w + (size_t)l*DI*DR, dt_b + (size_t)l*DI,
                                xcn, zn, dbl, dtn);

        scan3<<<NB*32, 256>>>(dtn, xcn, zn, dbl,
                              A_log + (size_t)l*DI*DS,
                              D_param + (size_t)l*DI, y);

        // out_proj: M=512, N=256, K=512, split-K=4 -> 128 blocks
        gemm_tn_split<<<dim3(DM/64, NTOK/64, SPLIT_OUT), 256>>>(
            y, out_proj_w + (size_t)l*DM*DI, outp, NTOK, DM, DI, DI/SPLIT_OUT);

        add_ln<<<NTOK, DM>>>(feat, norm_g, norm_b);
    }

    classifier<<<NB, 128>>>(feat, cls_w1, cls_b1, cls_w2, cls_b2, (float*)d_out);
}

// round 17
// speedup vs baseline: 1.5437x; 1.0109x over previous
#include <cuda_runtime.h>
#include <cuda_bf16.h>
#include <math.h>

// B=16, T=32 (early exit: only token 31 feeds classifier; all ops causal),
// DM=256, DI=512, DS=16, DR=16, DCONV=4, L=4.
// Multi-kernel pipeline (graph-captured). This round: scan4 — 4 states per
// thread (8 channels/warp, 2-shuffle reduce, float4 B/C loads).

#define NB      16
#define TT      32
#define NTOK    (NB*TT)      // 512
#define DM      256
#define DI      512
#define DS      16
#define DR      16
#define NL      4
#define SPLIT_IN  2
#define SPLIT_OUT 4

// scratch (device globals; no allocation allowed)
__device__ __align__(16) float g_feat[NTOK*DM];
__device__ __align__(16) float g_xzp [SPLIT_IN][NTOK*2*DI];
__device__ __align__(16) float g_dbl [NTOK*48];
__device__ __align__(16) float g_xcn [NTOK*DI];   // xc, [tok,d]
__device__ __align__(16) float g_zn  [NTOK*DI];   // z,  [tok,d]
__device__ __align__(16) float g_dtn [NTOK*DI];   // dt, [tok,d]
__device__ __align__(16) float g_y   [NTOK*DI];
__device__ __align__(16) float g_outp[SPLIT_OUT][NTOK*DM];

// ---------------------------------------------------------------------------
// featurize + token LN -> g_feat. One block per token.
// ---------------------------------------------------------------------------
__global__ void featurize(const float* __restrict__ x,
                          const float* __restrict__ ep,  const float* __restrict__ ef,
                          const float* __restrict__ ed,
                          const float* __restrict__ plw, const float* __restrict__ plb,
                          const float* __restrict__ piw, const float* __restrict__ pib,
                          const float* __restrict__ fw,  const float* __restrict__ fb,
                          const float* __restrict__ tg,  const float* __restrict__ tb,
                          float* __restrict__ feat)
{
    __shared__ float cat[136];
    __shared__ float red[DM];
    int tok = blockIdx.x;
    int b = tok >> 5, tl = tok & 31;
    const float* xr = x + (b*1024 + tl)*5;
    int d = threadIdx.x;
    if (d < 136) {
        float v;
        if (d < 32)       { int p = (int)xr[0]; p = min(max(p,0),255); v = ep[p*32 + d]; }
        else if (d < 64)  { v = xr[1]*plw[d-32] + plb[d-32]; }
        else if (d < 96)  { int f = (int)xr[2]; f = min(max(f,0),63);  v = ef[f*32 + (d-64)]; }
        else if (d < 128) { v = xr[3]*piw[d-96] + pib[d-96]; }
        else              { int dd = (int)xr[4]; dd = min(max(dd,0),1); v = ed[dd*8 + (d-128)]; }
        cat[d] = v;
    }
    __syncthreads();
    float acc = fb[d];
    const float* wrow = fw + d*136;
    #pragma unroll 8
    for (int j = 0; j < 136; j++) acc += cat[j]*wrow[j];
    red[d] = acc; __syncthreads();
    for (int off = 128; off; off >>= 1) { if (d < off) red[d] += red[d+off]; __syncthreads(); }
    float mean = red[0] * (1.f/DM); __syncthreads();
    float dv = acc - mean; red[d] = dv*dv; __syncthreads();
    for (int off = 128; off; off >>= 1) { if (d < off) red[d] += red[d+off]; __syncthreads(); }
    float var = red[0] * (1.f/DM);
    feat[tok*DM + d] = dv * rsqrtf(var + 1e-5f) * tg[d] + tb[d];
}

// ---------------------------------------------------------------------------
// Split-K SGEMM: Cp[z][M,N] = A[:, z*ks:(z+1)*ks] @ B^T slice.
// BM=BN=64, BK=16, 256 thr, 4x4 microtile. grid (N/64, M/64, S).
// ---------------------------------------------------------------------------
__global__ void gemm_tn_split(const float* __restrict__ A, const float* __restrict__ B,
                              float* __restrict__ Cp, int M, int N, int K, int ks)
{
    __shared__ __align__(16) float As[16][68];
    __shared__ __align__(16) float Bs[16][68];
    int bm = blockIdx.y*64, bn = blockIdx.x*64;
    int z  = blockIdx.z;
    int kbeg = z*ks, kend = kbeg + ks;
    float* C = Cp + (size_t)z*M*N;
    int tid = threadIdx.x;
    int lr = tid >> 2;
    int lk = (tid & 3) * 4;
    int ty = tid >> 4, tx = tid & 15;
    float acc[4][4] = {};
    for (int k0 = kbeg; k0 < kend; k0 += 16) {
        float4 av = *(const float4*)(A + (size_t)(bm+lr)*K + k0 + lk);
        float4 bv = *(const float4*)(B + (size_t)(bn+lr)*K + k0 + lk);
        As[lk+0][lr]=av.x; As[lk+1][lr]=av.y; As[lk+2][lr]=av.z; As[lk+3][lr]=av.w;
        Bs[lk+0][lr]=bv.x; Bs[lk+1][lr]=bv.y; Bs[lk+2][lr]=bv.z; Bs[lk+3][lr]=bv.w;
        __syncthreads();
        #pragma unroll
        for (int k = 0; k < 16; k++) {
            float4 a = *(const float4*)&As[k][ty*4];
            float4 bb = *(const float4*)&Bs[k][tx*4];
            float ar[4] = {a.x,a.y,a.z,a.w};
            float br[4] = {bb.x,bb.y,bb.z,bb.w};
            #pragma unroll
            for (int r = 0; r < 4; r++)
                #pragma unroll
                for (int c = 0; c < 4; c++)
                    acc[r][c] += ar[r]*br[c];
        }
        __syncthreads();
    }
    #pragma unroll
    for (int r = 0; r < 4; r++)
        *(float4*)(C + (size_t)(bm+ty*4+r)*N + bn + tx*4) =
            make_float4(acc[r][0],acc[r][1],acc[r][2],acc[r][3]);
}

// ---------------------------------------------------------------------------
// Fused: sum in_proj partials; causal conv(4)+SiLU; x_proj (48); softplus dt.
// Natural [tok,d] outputs. One block (512 thr) per token.
// ---------------------------------------------------------------------------
__global__ void fused_mid(const float* __restrict__ cw, const float* __restrict__ cb,
                          const float* __restrict__ xpw,
                          const float* __restrict__ dtw, const float* __restrict__ dtb,
                          float* __restrict__ xcn, float* __restrict__ zn,
                          float* __restrict__ dbl, float* __restrict__ dtn)
{
    __shared__ float xcs[DI];
    __shared__ float dbls[48];
    int tok = blockIdx.x;
    int tl = tok & 31;
    int d = threadIdx.x;
    const float* xz0 = &g_xzp[0][0];
    const float* xz1 = &g_xzp[1][0];

    float acc = cb[d];
    #pragma unroll
    for (int k = 0; k < 4; k++) {
        int tt = tl - 3 + k;
        if (tt >= 0) {
            size_t off = (size_t)(tok - 3 + k)*(2*DI) + d;
            acc += cw[d*4 + k] * (xz0[off] + xz1[off]);
        }
    }
    float s = acc / (1.f + __expf(-acc));   // SiLU
    xcs[d] = s;
    xcn[tok*DI + d] = s;
    size_t zo = (size_t)tok*(2*DI) + DI + d;
    zn[tok*DI + d] = xz0[zo] + xz1[zo];
    __syncthreads();

    int warp = d >> 5, lane = d & 31;
    #pragma unroll
    for (int i = 0; i < 3; i++) {
        int o = warp*3 + i;                 // 16 warps * 3 = 48 outputs
        const float* wr = xpw + o*DI;
        float p = 0.f;
        #pragma unroll
        for (int j = 0; j < 16; j++) p += xcs[j*32+lane]*wr[j*32+lane];
        #pragma unroll
        for (int off = 16; off; off >>= 1) p += __shfl_down_sync(0xffffffffu, p, off);
        if (lane == 0) { dbls[o] = p; dbl[tok*48 + o] = p; }
    }
    __syncthreads();

    float v = dtb[d];
    const float* dwr = dtw + d*DR;
    #pragma unroll
    for (int r = 0; r < DR; r++) v += dbls[r]*dwr[r];
    dtn[tok*DI + d] = (v > 20.f) ? v : log1pf(__expf(v));   // softplus
}

// ---------------------------------------------------------------------------
// Selective scan v4: one block per (batch, 64-channel chunk); serial t.
// Thread = (channel, 4-state group): 8 channels/warp, 2-shuffle reduce,
// float4 B/C loads. grid = NB*8 = 128 blocks, 256 threads.
// ---------------------------------------------------------------------------
__global__ void scan4(const float* __restrict__ dtn, const float* __restrict__ xcn,
                      const float* __restrict__ zn, const float* __restrict__ dbl,
                      const float* __restrict__ alog, const float* __restrict__ dp,
                      float* __restrict__ y)
{
    __shared__ __align__(16) float Bsm[512];
    __shared__ __align__(16) float Csm[512];
    __shared__ __align__(8)  float2 dw2[64*33];   // (dt, dt*xc) per (ch, t)
    __shared__ __align__(8)  float2 zx2[64*33];   // (z, D*xc)
    int b  = blockIdx.x >> 3;
    int d0 = (blockIdx.x & 7) * 64;
    int tid = threadIdx.x;

    // stage B/C: 512 elems
    #pragma unroll
    for (int i = tid; i < 512; i += 256) {
        int t = i >> 4, n = i & 15;
        const float* row = dbl + (b*TT + t)*48;
        Bsm[t*16+n] = row[16+n];
        Csm[t*16+n] = row[32+n];
    }
    // stage dt/xc/z: warp covers 32 consecutive channels of one t (coalesced)
    #pragma unroll
    for (int i = tid; i < 2048; i += 256) {
        int t = i >> 6, c = i & 63;
        size_t o = (size_t)(b*TT + t)*DI + d0 + c;
        float dtv = dtn[o];
        float xv  = xcn[o];
        dw2[c*33+t] = make_float2(dtv, dtv*xv);
        zx2[c*33+t] = make_float2(zn[o], dp[d0+c]*xv);
    }
    __syncthreads();

    int lane = tid & 31, warp = tid >> 5;
    int ch = warp*8 + (lane >> 2);   // 0..63
    int q  = lane & 3;               // state group
    int n0 = q*4;
    int d  = d0 + ch;
    const float* al = alog + (size_t)d*DS + n0;
    float A0 = -__expf(al[0]);
    float A1 = -__expf(al[1]);
    float A2 = -__expf(al[2]);
    float A3 = -__expf(al[3]);
    float h0 = 0.f, h1 = 0.f, h2 = 0.f, h3 = 0.f;

    #pragma unroll 4
    for (int t = 0; t < TT; t++) {
        float2 dw = dw2[ch*33+t];
        float4 Bv = *(const float4*)&Bsm[t*16+n0];
        float4 Cv = *(const float4*)&Csm[t*16+n0];
        h0 = __expf(dw.x*A0)*h0 + dw.y*Bv.x;
        h1 = __expf(dw.x*A1)*h1 + dw.y*Bv.y;
        h2 = __expf(dw.x*A2)*h2 + dw.y*Bv.z;
        h3 = __expf(dw.x*A3)*h3 + dw.y*Bv.w;
        float v = h0*Cv.x + h1*Cv.y + h2*Cv.z + h3*Cv.w;
        v += __shfl_xor_sync(0xffffffffu, v, 1);
        v += __shfl_xor_sync(0xffffffffu, v, 2);
        if (q == 0) {
            float2 zx = zx2[ch*33+t];
            float sz = zx.x / (1.f + __expf(-zx.x));
            y[(size_t)(b*TT+t)*DI + d] = (v + zx.y) * sz;
        }
    }
}

// ---------------------------------------------------------------------------
// residual + sum of 4 out_proj partials + LayerNorm -> feat. One block/token.
// ---------------------------------------------------------------------------
__global__ void add_ln(float* __restrict__ feat,
                       const float* __restrict__ g, const float* __restrict__ b)
{
    __shared__ float red[DM];
    int tok = blockIdx.x, d = threadIdx.x;
    size_t o = (size_t)tok*DM + d;
    float v = feat[o] + g_outp[0][o] + g_outp[1][o] + g_outp[2][o] + g_outp[3][o];
    red[d] = v; __syncthreads();
    for (int off = 128; off; off >>= 1) { if (d < off) red[d] += red[d+off]; __syncthreads(); }
    float mean = red[0] * (1.f/DM); __syncthreads();
    float dv = v - mean; red[d] = dv*dv; __syncthreads();
    for (int off = 128; off; off >>= 1) { if (d < off) red[d] += red[d+off]; __syncthreads(); }
    float var = red[0] * (1.f/DM);
    feat[o] = dv * rsqrtf(var + 1e-5f) * g[d] + b[d];
}

// ---------------------------------------------------------------------------
// Classifier on token 31 of each batch.
// ---------------------------------------------------------------------------
__global__ void classifier(const float* __restrict__ feat,
                           const float* __restrict__ w1, const float* __restrict__ b1,
                           const float* __restrict__ w2, const float* __restrict__ b2,
                           float* __restrict__ out)
{
    __shared__ float hs[128];
    int b = blockIdx.x, j = threadIdx.x;
    const float* fr = feat + (b*TT + 31)*DM;
    float acc = b1[j];
    const float* wr = w1 + j*DM;
    #pragma unroll 8
    for (int d = 0; d < DM; d++) acc += fr[d]*wr[d];
    hs[j] = fmaxf(acc, 0.f);
    __syncthreads();
    if (j < 2) {
        float o = b2[j];
        const float* w2r = w2 + j*128;
        #pragma unroll 8
        for (int k = 0; k < 128; k++) o += hs[k]*w2r[k];
        out[b*2 + j] = o;
    }
}

// ---------------------------------------------------------------------------
static float* sym_addr(const void* sym) {
    void* p = nullptr;
    cudaGetSymbolAddress(&p, sym);
    return (float*)p;
}

extern "C" void kernel_launch(void* const* d_in, const int* in_sizes, int n_in,
                              void* d_out, int out_size)
{
    const float* x         = (const float*)d_in[0];
    const float* emb_proto = (const float*)d_in[1];
    const float* emb_flags = (const float*)d_in[2];
    const float* emb_dir   = (const float*)d_in[3];
    const float* plw       = (const float*)d_in[4];
    const float* plb       = (const float*)d_in[5];
    const float* piw       = (const float*)d_in[6];
    const float* pib       = (const float*)d_in[7];
    const float* fusion_w  = (const float*)d_in[8];
    const float* fusion_b  = (const float*)d_in[9];
    const float* tok_g     = (const float*)d_in[10];
    const float* tok_b     = (const float*)d_in[11];
    const float* norm_g    = (const float*)d_in[12];
    const float* norm_b    = (const float*)d_in[13];
    const float* in_proj_w = (const float*)d_in[14];
    const float* conv_w    = (const float*)d_in[15];
    const float* conv_b    = (const float*)d_in[16];
    const float* x_proj_w  = (const float*)d_in[17];
    const float* dt_w      = (const float*)d_in[18];
    const float* dt_b      = (const float*)d_in[19];
    const float* A_log     = (const float*)d_in[20];
    const float* D_param   = (const float*)d_in[21];
    const float* out_proj_w= (const float*)d_in[22];
    const float* cls_w1    = (const float*)d_in[23];
    const float* cls_b1    = (const float*)d_in[24];
    const float* cls_w2    = (const float*)d_in[25];
    const float* cls_b2    = (const float*)d_in[26];

    static float *feat=nullptr, *xzp, *dbl, *xcn, *zn, *dtn, *y, *outp;
    if (!feat) {
        feat = sym_addr(g_feat); xzp = sym_addr(g_xzp); dbl = sym_addr(g_dbl);
        xcn = sym_addr(g_xcn);   zn = sym_addr(g_zn); dtn = sym_addr(g_dtn);
        y = sym_addr(g_y);       outp = sym_addr(g_outp);
    }

    featurize<<<NTOK, DM>>>(x, emb_proto, emb_flags, emb_dir,
                            plw, plb, piw, pib,
                            fusion_w, fusion_b, tok_g, tok_b, feat);

    for (int l = 0; l < NL; l++) {
        // in_proj: M=512, N=1024, K=256, split-K=2 -> 256 blocks
        gemm_tn_split<<<dim3((2*DI)/64, NTOK/64, SPLIT_IN), 256>>>(
            feat, in_proj_w + (size_t)l*2*DI*DM, xzp, NTOK, 2*DI, DM, DM/SPLIT_IN);

        fused_mid<<<NTOK, DI>>>(conv_w + (size_t)l*DI*4, conv_b + (size_t)l*DI,
                                x_proj_w + (size_t)l*48*DI,
                                dt_w + (size_t)l*DI*DR, dt_b + (size_t)l*DI,
                                xcn, zn, dbl, dtn);

        scan4<<<NB*8, 256>>>(dtn, xcn, zn, dbl,
                             A_log + (size_t)l*DI*DS,
                             D_param + (size_t)l*DI, y);

        // out_proj: M=512, N=256, K=512, split-K=4 -> 128 blocks
        gemm_tn_split<<<dim3(DM/64, NTOK/64, SPLIT_OUT), 256>>>(
            y, out_proj_w + (size_t)l*DM*DI, outp, NTOK, DM, DI, DI/SPLIT_OUT);

        add_ln<<<NTOK, DM>>>(feat, norm_g, norm_b);
    }

    classifier<<<NB, 128>>>(feat, cls_w1, cls_b1, cls_w2, cls_b2, (float*)d_out);
}